// round 8
// baseline (speedup 1.0000x reference)
#include <cuda_runtime.h>
#include <cuda_bf16.h>
#include <cstdint>

#define BATCH 16384
#define LSEQ  256
#define CH    32
#define EPSBN 1e-5
#define LOG2PI 1.8378770664093453f

typedef unsigned long long ull;

// ---------------- scratch (device-global; no runtime alloc allowed) -------
__device__ float  g_buf1[(size_t)BATCH*CH*LSEQ];   // conv1 output (pre-BN)
__device__ float  g_buf2[(size_t)BATCH*CH*LSEQ];   // h1 (pre-BN)
__device__ float  g_buf3[(size_t)BATCH*CH*LSEQ];   // h2 (pre-BN)
__device__ float  g_ctx [(size_t)BATCH*64];        // context vectors
__device__ double g_stat[3][2][32];                // [stage][sum|sumsq][channel]

// ---------------- packed fp32x2 helpers (FFMA2, conv1/coupling) ------------
__device__ __forceinline__ ull pk(float lo, float hi){
    ull r; asm("mov.b64 %0, {%1,%2};" : "=l"(r) : "f"(lo), "f"(hi)); return r;
}
__device__ __forceinline__ void upk(ull v, float& lo, float& hi){
    asm("mov.b64 {%0,%1}, %2;" : "=f"(lo), "=f"(hi) : "l"(v));
}
__device__ __forceinline__ void ffma2_acc(ull& a, ull b, ull c){
    asm("fma.rn.f32x2 %0, %1, %2, %0;" : "+l"(a) : "l"(b), "l"(c));
}
__device__ __forceinline__ float wred32(float v){
#pragma unroll
    for (int o = 16; o > 0; o >>= 1) v += __shfl_xor_sync(0xffffffffu, v, o);
    return v;
}
__device__ __forceinline__ uint32_t smem_u32(const void* p){
    uint32_t a;
    asm("{ .reg .u64 t; cvta.to.shared.u64 t, %1; cvt.u32.u64 %0, t; }" : "=r"(a) : "l"(p));
    return a;
}

// ---------------- warp-MMA helpers (baseline PTX, works on sm_103) --------
#define LDMATRIX_X4(a0,a1,a2,a3, addr) \
    asm volatile("ldmatrix.sync.aligned.m8n8.x4.shared.b16 {%0,%1,%2,%3}, [%4];" \
        : "=r"(a0), "=r"(a1), "=r"(a2), "=r"(a3) : "r"(addr))
#define LDS32(x, addr) \
    asm volatile("ld.shared.b32 %0, [%1];" : "=r"(x) : "r"(addr))
#define MMA16816(d, a0,a1,a2,a3, b0,b1) \
    asm volatile("mma.sync.aligned.m16n8k16.row.col.f32.bf16.bf16.f32 " \
        "{%0,%1,%2,%3}, {%4,%5,%6,%7}, {%8,%9}, {%0,%1,%2,%3};" \
        : "+f"((d)[0]), "+f"((d)[1]), "+f"((d)[2]), "+f"((d)[3]) \
        : "r"(a0), "r"(a1), "r"(a2), "r"(a3), "r"(b0), "r"(b1))

// strides (bf16 units / f32 units)
#define STRA  216
#define STRB1 200
#define STRB2 104
#define STRXS 36
// smem byte offsets
#define SMA   0                        // 128*216*2 = 55296
#define SMB1  55296                    // 32*200*2  = 12800
#define SMB2  68096                    // 32*104*2  = 6656
#define SMXS  74752                    // 130*36*4  = 18720
#define SMSC  93472                    // sc/sh/cbs 3*32*4
#define SMRED 93856                    // redS/redQ 2*128*4
#define SM_TOTAL_M 94880

// ---------------- K0: zero the stat accumulators ---------------------------
__global__ void k_init_stats(){
    int t = threadIdx.x;
    if (t < 192) (&g_stat[0][0][0])[t] = 0.0;
}

// ---------------- K1: conv1 (4->32, k=5, SAME) + bias, stats stage 0 -------
__global__ __launch_bounds__(128) void k_conv1(const float* __restrict__ curve,
                                               const float* __restrict__ w,
                                               const float* __restrict__ bias){
    const int b = blockIdx.x;
    const int t = threadIdx.x;
    extern __shared__ ull smu[];
    ull*   wd  = smu;                     // dup weights: ull[(i*32+c)*8 + k], 1024
    float* cbs = (float*)(wd + 1024);
    float* xin = cbs + 32;                // 4*272
    float* redS= xin + 4*272;
    float* redQ= redS + 32;

    if (t < 32) cbs[t] = bias[t];
    for (int idx = t; idx < 4*272; idx += 128){
        int i = idx / 272, p = idx - i*272, l = p - 2;
        xin[idx] = (l >= 0 && l < LSEQ) ? curve[((size_t)b*4 + i)*LSEQ + l] : 0.f;
    }
    for (int idx = t; idx < 4*32*8; idx += 128){
        int i = idx >> 8, rem = idx & 255, c = rem >> 3, k = rem & 7;
        float v = (k < 5) ? w[c*20 + i*5 + k] : 0.f;
        ((float2*)wd)[idx] = make_float2(v, v);
    }
    __syncthreads();

    const int wrp = t >> 5, lane = t & 31;
    const int c0 = wrp*8, l0 = lane*8;

    ull A[8][4];
#pragma unroll
    for (int cc = 0; cc < 8; cc++){
        float cb = cbs[c0 + cc];
#pragma unroll
        for (int p = 0; p < 4; p++) A[cc][p] = pk(cb, cb);
    }
#pragma unroll
    for (int i = 0; i < 4; i++){
        const float* xb = xin + i*272 + l0;
        float4 u0 = *(const float4*)(xb);
        float4 u1 = *(const float4*)(xb + 4);
        float4 u2 = *(const float4*)(xb + 8);
        float xm[12] = {u0.x,u0.y,u0.z,u0.w, u1.x,u1.y,u1.z,u1.w, u2.x,u2.y,u2.z,u2.w};
        ull P[11];
#pragma unroll
        for (int m = 0; m < 11; m++) P[m] = pk(xm[m], xm[m+1]);
        const ull* wp = wd + (i*32 + c0)*8;
#pragma unroll
        for (int cc = 0; cc < 8; cc++){
            ulonglong2 W01 = *(const ulonglong2*)(wp + cc*8);
            ulonglong2 W23 = *(const ulonglong2*)(wp + cc*8 + 2);
            ull W4 = wp[cc*8 + 4];
#pragma unroll
            for (int p = 0; p < 4; p++){
                ffma2_acc(A[cc][p], P[2*p+0], W01.x);
                ffma2_acc(A[cc][p], P[2*p+1], W01.y);
                ffma2_acc(A[cc][p], P[2*p+2], W23.x);
                ffma2_acc(A[cc][p], P[2*p+3], W23.y);
                ffma2_acc(A[cc][p], P[2*p+4], W4);
            }
        }
    }

    float* outp = g_buf1 + (size_t)b*CH*LSEQ;
#pragma unroll
    for (int cc = 0; cc < 8; cc++){
        float v[8];
#pragma unroll
        for (int p = 0; p < 4; p++) upk(A[cc][p], v[2*p], v[2*p+1]);
        int c = c0 + cc;
        *(float4*)(outp + c*LSEQ + l0)     = make_float4(v[0],v[1],v[2],v[3]);
        *(float4*)(outp + c*LSEQ + l0 + 4) = make_float4(v[4],v[5],v[6],v[7]);
        float s = 0.f, q = 0.f;
#pragma unroll
        for (int m = 0; m < 8; m++){ s += v[m]; q += v[m]*v[m]; }
        s = wred32(s); q = wred32(q);
        if (lane == 0){ redS[c] = s; redQ[c] = q; }
    }
    __syncthreads();
    if (t < 32){
        atomicAdd(&g_stat[0][0][t], (double)redS[t]);
        atomicAdd(&g_stat[0][1][t], (double)redQ[t]);
    }
}

// ---------------- K2/K3: bn+relu -> conv(32->32,k3) via HMMA (mma.sync) ----
// One CTA = half sample (M=128 rows = L positions), N=32 channels.
// Split-bf16: D = [xh|xl](K=192)@[wh|wh]^T + xh(K=96)@[wl]^T, fp32 accum.
__global__ __launch_bounds__(128) void k_rbmma(int pass,
                                               const float* __restrict__ gam,
                                               const float* __restrict__ bet,
                                               const float* __restrict__ w,
                                               const float* __restrict__ cbias){
    const int b = blockIdx.x >> 1;
    const int lbase = (blockIdx.x & 1) * 128;
    const int t = threadIdx.x;
    const int lane = t & 31, wrp = t >> 5;
    const float* bufIn = (pass == 0) ? g_buf1 : g_buf2;
    float* bufOut = (pass == 0) ? g_buf2 : g_buf3;
    const int stIn = pass, stOut = pass + 1;

    extern __shared__ char smc[];
    const uint32_t smb = smem_u32(smc);
    __nv_bfloat16* Abuf = (__nv_bfloat16*)(smc + SMA);
    __nv_bfloat16* B1   = (__nv_bfloat16*)(smc + SMB1);
    __nv_bfloat16* B2   = (__nv_bfloat16*)(smc + SMB2);
    float* xs  = (float*)(smc + SMXS);
    float* sc  = (float*)(smc + SMSC);
    float* sh  = sc + 32;
    float* cbs = sh + 32;
    float* redS= (float*)(smc + SMRED);
    float* redQ= redS + 128;

    // phase 0: BN constants + B tiles (weights)
    if (t < 32){
        const double N = (double)BATCH * (double)LSEQ;
        double S = g_stat[stIn][0][t], Q = g_stat[stIn][1][t];
        double m = S / N, v = Q / N - m*m;
        double s = (double)gam[t] / sqrt(v + EPSBN);
        sc[t] = (float)s;
        sh[t] = (float)((double)bet[t] - m*s);
        cbs[t] = cbias[t];
    }
    for (int idx = t; idx < 32*192; idx += 128){
        int n = idx / 192, k = idx - n*192;
        int kp = (k >= 96) ? k - 96 : k;
        int i = kp & 31, kk = kp >> 5;
        B1[n*STRB1 + k] = __float2bfloat16(w[n*96 + i*3 + kk]);
    }
    for (int idx = t; idx < 32*96; idx += 128){
        int n = idx / 96, k = idx - n*96;
        int i = k & 31, kk = k >> 5;
        float v = w[n*96 + i*3 + kk];
        __nv_bfloat16 h = __float2bfloat16(v);
        B2[n*STRB2 + k] = __float2bfloat16(v - __bfloat162float(h));
    }
    __syncthreads();

    // phase 1: bn+relu input -> xs[l'][i], l' = 0..129 (l = lbase + l' - 1)
    {
        const float* inp = bufIn + (size_t)b*CH*LSEQ;
        for (int idx = t; idx < 32*130; idx += 128){
            int i = idx / 130, lp = idx - i*130;
            int l = lbase + lp - 1;
            float y = 0.f;
            if (l >= 0 && l < LSEQ) y = fmaxf(sc[i]*inp[i*LSEQ + l] + sh[i], 0.f);
            xs[lp*STRXS + i] = y;
        }
    }
    __syncthreads();

    // phase 2: im2col A fill (bf16 hi at cols k, lo at cols 96+k), pairwise
    for (int idx = t; idx < 128*48; idx += 128){
        int p = idx / 48, kp = idx - p*48;
        int kk = kp >> 4, ip = kp & 15, i = ip*2;
        int k = kk*32 + i;
        float2 y2 = *(const float2*)&xs[(p + kk)*STRXS + i];
        uint32_t hp;
        asm("cvt.rn.bf16x2.f32 %0, %1, %2;" : "=r"(hp) : "f"(y2.y), "f"(y2.x));
        float h0 = __uint_as_float(hp << 16);
        float h1 = __uint_as_float(hp & 0xffff0000u);
        float l0 = y2.x - h0, l1 = y2.y - h1;
        uint32_t lp2;
        asm("cvt.rn.bf16x2.f32 %0, %1, %2;" : "=r"(lp2) : "f"(l1), "f"(l0));
        *(uint32_t*)((char*)Abuf + (p*STRA + k)*2)      = hp;
        *(uint32_t*)((char*)Abuf + (p*STRA + 96 + k)*2) = lp2;
    }
    __syncthreads();

    // mainloop: warp wrp owns M rows [wrp*32, wrp*32+32)
    const int m0 = wrp*32;
    float d[2][4][4];
#pragma unroll
    for (int tm = 0; tm < 2; tm++)
#pragma unroll
        for (int tn = 0; tn < 4; tn++)
#pragma unroll
            for (int e = 0; e < 4; e++) d[tm][tn][e] = 0.f;

    const uint32_t a_base = smb + SMA +
        (uint32_t)(( (m0 + (lane & 15))*STRA + ((lane >= 16) ? 8 : 0) ) * 2);
    const uint32_t b1_base = smb + SMB1 + (uint32_t)(( (lane >> 2)*STRB1 + (lane & 3)*2 ) * 2);
    const uint32_t b2_base = smb + SMB2 + (uint32_t)(( (lane >> 2)*STRB2 + (lane & 3)*2 ) * 2);

#pragma unroll
    for (int ks = 0; ks < 12; ks++){
        uint32_t bf[4][2];
#pragma unroll
        for (int tn = 0; tn < 4; tn++){
            uint32_t addr = b1_base + (uint32_t)((tn*8*STRB1 + ks*16) * 2);
            LDS32(bf[tn][0], addr);
            LDS32(bf[tn][1], addr + 16);
        }
#pragma unroll
        for (int tm = 0; tm < 2; tm++){
            uint32_t a0,a1,a2,a3;
            LDMATRIX_X4(a0,a1,a2,a3, a_base + (uint32_t)(tm*16*STRA*2 + ks*32));
#pragma unroll
            for (int tn = 0; tn < 4; tn++)
                MMA16816(d[tm][tn], a0,a1,a2,a3, bf[tn][0], bf[tn][1]);
        }
    }
#pragma unroll
    for (int ks = 0; ks < 6; ks++){
        uint32_t bf[4][2];
#pragma unroll
        for (int tn = 0; tn < 4; tn++){
            uint32_t addr = b2_base + (uint32_t)((tn*8*STRB2 + ks*16) * 2);
            LDS32(bf[tn][0], addr);
            LDS32(bf[tn][1], addr + 16);
        }
#pragma unroll
        for (int tm = 0; tm < 2; tm++){
            uint32_t a0,a1,a2,a3;
            LDMATRIX_X4(a0,a1,a2,a3, a_base + (uint32_t)(tm*16*STRA*2 + ks*32));
#pragma unroll
            for (int tn = 0; tn < 4; tn++)
                MMA16816(d[tm][tn], a0,a1,a2,a3, bf[tn][0], bf[tn][1]);
        }
    }

    // epilogue: bias, store, per-channel stats
    float* outp = bufOut + (size_t)b*CH*LSEQ + lbase;
    float ps[8], pq[8];
#pragma unroll
    for (int j = 0; j < 8; j++){ ps[j] = 0.f; pq[j] = 0.f; }
#pragma unroll
    for (int tm = 0; tm < 2; tm++){
        int r0 = m0 + tm*16 + (lane >> 2);
#pragma unroll
        for (int tn = 0; tn < 4; tn++){
            int c0 = tn*8 + (lane & 3)*2;
            float v00 = d[tm][tn][0] + cbs[c0];
            float v01 = d[tm][tn][1] + cbs[c0+1];
            float v10 = d[tm][tn][2] + cbs[c0];
            float v11 = d[tm][tn][3] + cbs[c0+1];
            outp[c0*LSEQ + r0]         = v00;
            outp[(c0+1)*LSEQ + r0]     = v01;
            outp[c0*LSEQ + r0 + 8]     = v10;
            outp[(c0+1)*LSEQ + r0 + 8] = v11;
            ps[tn*2+0] += v00 + v10;  pq[tn*2+0] += v00*v00 + v10*v10;
            ps[tn*2+1] += v01 + v11;  pq[tn*2+1] += v01*v01 + v11*v11;
        }
    }
#pragma unroll
    for (int j = 0; j < 8; j++){
#pragma unroll
        for (int o = 4; o < 32; o <<= 1){
            ps[j] += __shfl_xor_sync(0xffffffffu, ps[j], o);
            pq[j] += __shfl_xor_sync(0xffffffffu, pq[j], o);
        }
    }
    if (lane < 4){
#pragma unroll
        for (int tn = 0; tn < 4; tn++){
#pragma unroll
            for (int p = 0; p < 2; p++){
                int c = tn*8 + lane*2 + p;
                redS[wrp*32 + c] = ps[tn*2+p];
                redQ[wrp*32 + c] = pq[tn*2+p];
            }
        }
    }
    __syncthreads();
    if (t < 32){
        atomicAdd(&g_stat[stOut][0][t],
                  (double)(redS[t] + redS[32+t] + redS[64+t] + redS[96+t]));
        atomicAdd(&g_stat[stOut][1][t],
                  (double)(redQ[t] + redQ[32+t] + redQ[64+t] + redQ[96+t]));
    }
}

// ---------------- K4: bn0+relu, bn2, residual+relu, mean-pool, linear+tanh -
__global__ __launch_bounds__(256) void k_pool_ctx(const float* __restrict__ gamma1,
                                                  const float* __restrict__ beta1,
                                                  const float* __restrict__ gamma3,
                                                  const float* __restrict__ beta3,
                                                  const float* __restrict__ lin_w,
                                                  const float* __restrict__ lin_b){
    const int b = blockIdx.x;
    const int t = threadIdx.x;
    __shared__ float sc0[32], sh0[32], sc2[32], sh2[32];
    __shared__ float red[32][8];
    __shared__ float pooled[32];

    if (t < 32){
        const double N = (double)BATCH * (double)LSEQ;
        { double S = g_stat[0][0][t], Q = g_stat[0][1][t];
          double m = S/N, v = Q/N - m*m;
          double s = (double)gamma1[t] / sqrt(v + EPSBN);
          sc0[t] = (float)s; sh0[t] = (float)((double)beta1[t] - m*s); }
        { double S = g_stat[2][0][t], Q = g_stat[2][1][t];
          double m = S/N, v = Q/N - m*m;
          double s = (double)gamma3[t] / sqrt(v + EPSBN);
          sc2[t] = (float)s; sh2[t] = (float)((double)beta3[t] - m*s); }
    }
    __syncthreads();

    const float* p1 = g_buf1 + (size_t)b*CH*LSEQ;
    const float* p2 = g_buf3 + (size_t)b*CH*LSEQ;
    const int wid = t >> 5, lane = t & 31;
#pragma unroll 1
    for (int c = 0; c < 32; c++){
        float y1 = p1[c*LSEQ + t];
        float h2 = p2[c*LSEQ + t];
        float x1 = fmaxf(sc0[c]*y1 + sh0[c], 0.f);
        float x2 = fmaxf(sc2[c]*h2 + sh2[c] + x1, 0.f);
        float s = wred32(x2);
        if (lane == 0) red[c][wid] = s;
    }
    __syncthreads();
    if (t < 32){
        float s = 0.f;
#pragma unroll
        for (int wI = 0; wI < 8; wI++) s += red[t][wI];
        pooled[t] = s * (1.f/(float)LSEQ);
    }
    __syncthreads();
    if (t < 64){
        float acc = lin_b[t];
#pragma unroll
        for (int c = 0; c < 32; c++) acc += pooled[c]*lin_w[c*64 + t];
        g_ctx[(size_t)b*64 + t] = tanhf(acc);
    }
}

// ---------------- K5: 10 coupling layers, 64 rows per block, all in smem ---
__global__ __launch_bounds__(256) void k_coupling(const float* __restrict__ zin,
                                                  const float* __restrict__ W1,
                                                  const float* __restrict__ B1w,
                                                  const float* __restrict__ W2,
                                                  const float* __restrict__ B2w,
                                                  const float* __restrict__ W3,
                                                  const float* __restrict__ B3w,
                                                  float* __restrict__ outp){
    const int t = threadIdx.x;
    const int rowBase = blockIdx.x * 64;
    extern __shared__ float sm[];
    float* nin = sm;
    float* hA  = nin + 64*76;
    float* hB  = hA  + 64*132;
    float* zz  = hB  + 64*132;
    float* ob  = zz  + 64*12;
    float* ldv = ob  + 64*20;

    for (int idx = t; idx < 64*9; idx += 256){
        int r = idx/9, j = idx - r*9;
        zz[r*12 + j] = zin[(size_t)(rowBase + r)*9 + j];
    }
    for (int idx = t; idx < 64*64; idx += 256){
        int r = idx >> 6, j = idx & 63;
        nin[r*76 + 9 + j] = g_ctx[(size_t)(rowBase + r)*64 + j];
    }
    if (t < 64) ldv[t] = 0.f;
    __syncthreads();

    const int jc = t & 31;
    const int r0 = (t >> 5) * 8;

    for (int layer = 0; layer < 10; ++layer){
        if (t < 64){
#pragma unroll
            for (int j = 0; j < 9; j++){
                float m = (((j + layer) & 1) == 0) ? 1.f : 0.f;
                nin[t*76 + j] = zz[t*12 + j] * m;
            }
        }
        __syncthreads();
        {
            const float* Wl = W1 + (size_t)layer*73*128;
            float4 bb = *(const float4*)(B1w + layer*128 + 4*jc);
            ull acc[8][2];
#pragma unroll
            for (int r = 0; r < 8; r++){ acc[r][0] = pk(bb.x, bb.y); acc[r][1] = pk(bb.z, bb.w); }
#pragma unroll 2
            for (int i = 0; i < 73; i++){
                ulonglong2 wv = *(const ulonglong2*)(Wl + i*128 + 4*jc);
#pragma unroll
                for (int r = 0; r < 8; r++){
                    float x = nin[(r0 + r)*76 + i];
                    ull xx = pk(x, x);
                    ffma2_acc(acc[r][0], xx, wv.x);
                    ffma2_acc(acc[r][1], xx, wv.y);
                }
            }
#pragma unroll
            for (int r = 0; r < 8; r++){
                float v0,v1,v2,v3;
                upk(acc[r][0], v0, v1); upk(acc[r][1], v2, v3);
                *(float4*)(hA + (r0 + r)*132 + 4*jc) =
                    make_float4(fmaxf(v0,0.f), fmaxf(v1,0.f), fmaxf(v2,0.f), fmaxf(v3,0.f));
            }
        }
        __syncthreads();
        {
            const float* Wl = W2 + (size_t)layer*128*128;
            float4 bb = *(const float4*)(B2w + layer*128 + 4*jc);
            ull acc[8][2];
#pragma unroll
            for (int r = 0; r < 8; r++){ acc[r][0] = pk(bb.x, bb.y); acc[r][1] = pk(bb.z, bb.w); }
#pragma unroll 2
            for (int i = 0; i < 128; i++){
                ulonglong2 wv = *(const ulonglong2*)(Wl + i*128 + 4*jc);
#pragma unroll
                for (int r = 0; r < 8; r++){
                    float x = hA[(r0 + r)*132 + i];
                    ull xx = pk(x, x);
                    ffma2_acc(acc[r][0], xx, wv.x);
                    ffma2_acc(acc[r][1], xx, wv.y);
                }
            }
#pragma unroll
            for (int r = 0; r < 8; r++){
                float v0,v1,v2,v3;
                upk(acc[r][0], v0, v1); upk(acc[r][1], v2, v3);
                *(float4*)(hB + (r0 + r)*132 + 4*jc) =
                    make_float4(fmaxf(v0,0.f), fmaxf(v1,0.f), fmaxf(v2,0.f), fmaxf(v3,0.f));
            }
        }
        __syncthreads();
        {
            const float* Wl = W3 + (size_t)layer*128*18;
            const int r = t >> 2, q = t & 3;
            float acc[5] = {0.f,0.f,0.f,0.f,0.f};
#pragma unroll 2
            for (int i = 0; i < 128; i++){
                float x = hB[r*132 + i];
#pragma unroll
                for (int k = 0; k < 5; k++){
                    int j = q + 4*k;
                    if (j < 18) acc[k] = fmaf(x, __ldg(Wl + i*18 + j), acc[k]);
                }
            }
#pragma unroll
            for (int k = 0; k < 5; k++){
                int j = q + 4*k;
                if (j < 18) ob[r*20 + j] = acc[k] + B3w[layer*18 + j];
            }
        }
        __syncthreads();
        if (t < 64){
            float ldl = ldv[t];
#pragma unroll
            for (int j = 0; j < 9; j++){
                if (((j + layer) & 1) != 0){
                    float s  = tanhf(ob[t*20 + j]);
                    float tt = ob[t*20 + 9 + j];
                    zz[t*12 + j] = zz[t*12 + j]*expf(s) + tt;
                    ldl += s;
                }
            }
            ldv[t] = ldl;
        }
        __syncthreads();
    }

    if (t < 64){
        float lp = 0.f;
#pragma unroll
        for (int j = 0; j < 9; j++){
            float z = zz[t*12 + j];
            lp += LOG2PI + z*z;
        }
        outp[rowBase + t] = ldv[t] - 0.5f*lp;
    }
}

// ---------------- launch ----------------------------------------------------
extern "C" void kernel_launch(void* const* d_in, const int* in_sizes, int n_in,
                              void* d_out, int out_size){
    const float* inputs  = (const float*)d_in[0];
    const float* curve   = (const float*)d_in[1];
    const float* conv1_w = (const float*)d_in[2];
    const float* conv1_b = (const float*)d_in[3];
    const float* bn1_g   = (const float*)d_in[4];
    const float* bn1_b   = (const float*)d_in[5];
    const float* rb_w1   = (const float*)d_in[6];
    const float* rb_b1   = (const float*)d_in[7];
    const float* rb_g1   = (const float*)d_in[8];
    const float* rb_be1  = (const float*)d_in[9];
    const float* rb_w2   = (const float*)d_in[10];
    const float* rb_b2   = (const float*)d_in[11];
    const float* rb_g2   = (const float*)d_in[12];
    const float* rb_be2  = (const float*)d_in[13];
    const float* lin_w   = (const float*)d_in[14];
    const float* lin_b   = (const float*)d_in[15];
    const float* W1      = (const float*)d_in[16];
    const float* B1      = (const float*)d_in[17];
    const float* W2      = (const float*)d_in[18];
    const float* B2      = (const float*)d_in[19];
    const float* W3      = (const float*)d_in[20];
    const float* B3      = (const float*)d_in[21];
    float* out = (float*)d_out;

    const int smem1 = 1024*8 + (32 + 4*272 + 32 + 32) * 4;
    const int smemC = (64*76 + 64*132*2 + 64*12 + 64*20 + 64) * 4;

    cudaFuncSetAttribute(k_conv1,    cudaFuncAttributeMaxDynamicSharedMemorySize, smem1);
    cudaFuncSetAttribute(k_rbmma,    cudaFuncAttributeMaxDynamicSharedMemorySize, SM_TOTAL_M);
    cudaFuncSetAttribute(k_coupling, cudaFuncAttributeMaxDynamicSharedMemorySize, smemC);

    k_init_stats<<<1, 192>>>();
    k_conv1<<<BATCH, 128, smem1>>>(curve, conv1_w, conv1_b);
    k_rbmma<<<BATCH*2, 128, SM_TOTAL_M>>>(0, bn1_g, bn1_b, rb_w1, rb_b1);
    k_rbmma<<<BATCH*2, 128, SM_TOTAL_M>>>(1, rb_g1, rb_be1, rb_w2, rb_b2);
    k_pool_ctx<<<BATCH, 256>>>(bn1_g, bn1_b, rb_g2, rb_be2, lin_w, lin_b);
    k_coupling<<<BATCH/64, 256, smemC>>>(inputs, W1, B1, W2, B2, W3, B3, out);
}

// round 9
// speedup vs baseline: 1.2475x; 1.2475x over previous
#include <cuda_runtime.h>
#include <cuda_bf16.h>
#include <cstdint>

#define BATCH 16384
#define LSEQ  256
#define CH    32
#define EPSBN 1e-5
#define LOG2PI 1.8378770664093453f

typedef unsigned long long ull;

// ---------------- scratch (device-global; no runtime alloc allowed) -------
__device__ float  g_buf1[(size_t)BATCH*CH*LSEQ];   // conv1 output (pre-BN)
__device__ float  g_buf2[(size_t)BATCH*CH*LSEQ];   // h1 (pre-BN)
__device__ float  g_buf3[(size_t)BATCH*CH*LSEQ];   // h2 (pre-BN)
__device__ float  g_ctx [(size_t)BATCH*64];        // context vectors
__device__ double g_stat[3][2][32];                // [stage][sum|sumsq][channel]
__device__ uint4  g_whl[2][832];                   // [pass][wh(416 uint4) | wl(416)]

// ---------------- packed fp32x2 helpers (FFMA2, conv1/coupling) ------------
__device__ __forceinline__ ull pk(float lo, float hi){
    ull r; asm("mov.b64 %0, {%1,%2};" : "=l"(r) : "f"(lo), "f"(hi)); return r;
}
__device__ __forceinline__ void upk(ull v, float& lo, float& hi){
    asm("mov.b64 {%0,%1}, %2;" : "=f"(lo), "=f"(hi) : "l"(v));
}
__device__ __forceinline__ void ffma2_acc(ull& a, ull b, ull c){
    asm("fma.rn.f32x2 %0, %1, %2, %0;" : "+l"(a) : "l"(b), "l"(c));
}
__device__ __forceinline__ float wred32(float v){
#pragma unroll
    for (int o = 16; o > 0; o >>= 1) v += __shfl_xor_sync(0xffffffffu, v, o);
    return v;
}
__device__ __forceinline__ uint32_t smem_u32(const void* p){
    uint32_t a;
    asm("{ .reg .u64 t; cvta.to.shared.u64 t, %1; cvt.u32.u64 %0, t; }" : "=r"(a) : "l"(p));
    return a;
}

// ---------------- warp-MMA helpers (baseline PTX, works on sm_103) --------
#define LDMATRIX_X4(a0,a1,a2,a3, addr) \
    asm volatile("ldmatrix.sync.aligned.m8n8.x4.shared.b16 {%0,%1,%2,%3}, [%4];" \
        : "=r"(a0), "=r"(a1), "=r"(a2), "=r"(a3) : "r"(addr))
#define LDS32(x, addr) \
    asm volatile("ld.shared.b32 %0, [%1];" : "=r"(x) : "r"(addr))
#define MMA16816(d, a0,a1,a2,a3, b0,b1) \
    asm volatile("mma.sync.aligned.m16n8k16.row.col.f32.bf16.bf16.f32 " \
        "{%0,%1,%2,%3}, {%4,%5,%6,%7}, {%8,%9}, {%0,%1,%2,%3};" \
        : "+f"((d)[0]), "+f"((d)[1]), "+f"((d)[2]), "+f"((d)[3]) \
        : "r"(a0), "r"(a1), "r"(a2), "r"(a3), "r"(b0), "r"(b1))

// strides (bf16 units)
#define STRA  216
#define STRB  104
// smem byte offsets for k_rbmma
#define SMA    0            // 128*216*2 = 55296
#define SMWH   55296        // 32*104*2  = 6656
#define SMWL   61952        // 6656
#define SMSC   68608        // sc[32], sh[32], cbs[32]
#define SMRED  68992        // redS[8][32], redQ[8][32] = 2048
#define SM_TOTAL_M 71040

// ---------------- K0: zero stats + pre-convert bf16 weight tiles -----------
__global__ void k_prep(const float* __restrict__ w1, const float* __restrict__ w2){
    const int t = threadIdx.x;
    if (t < 192) (&g_stat[0][0][0])[t] = 0.0;
#pragma unroll 1
    for (int pass = 0; pass < 2; pass++){
        const float* w = pass ? w2 : w1;
        __nv_bfloat16* wh = (__nv_bfloat16*)&g_whl[pass][0];
        __nv_bfloat16* wl = wh + 32*STRB;
        for (int idx = t; idx < 32*STRB; idx += 256){
            int n = idx / STRB, k = idx - n*STRB;
            __nv_bfloat16 h = __float2bfloat16(0.f), lo = h;
            if (k < 96){
                int i = k & 31, kk = k >> 5;
                float v = w[n*96 + i*3 + kk];
                h = __float2bfloat16(v);
                lo = __float2bfloat16(v - __bfloat162float(h));
            }
            wh[idx] = h;
            wl[idx] = lo;
        }
    }
}

// ---------------- K1: conv1 (4->32, k=5, SAME) + bias, stats stage 0 -------
__global__ __launch_bounds__(128) void k_conv1(const float* __restrict__ curve,
                                               const float* __restrict__ w,
                                               const float* __restrict__ bias){
    const int b = blockIdx.x;
    const int t = threadIdx.x;
    extern __shared__ ull smu[];
    ull*   wd  = smu;                     // dup weights: ull[(i*32+c)*8 + k], 1024
    float* cbs = (float*)(wd + 1024);
    float* xin = cbs + 32;                // 4*272
    float* redS= xin + 4*272;
    float* redQ= redS + 32;

    if (t < 32) cbs[t] = bias[t];
    for (int idx = t; idx < 4*272; idx += 128){
        int i = idx / 272, p = idx - i*272, l = p - 2;
        xin[idx] = (l >= 0 && l < LSEQ) ? curve[((size_t)b*4 + i)*LSEQ + l] : 0.f;
    }
    for (int idx = t; idx < 4*32*8; idx += 128){
        int i = idx >> 8, rem = idx & 255, c = rem >> 3, k = rem & 7;
        float v = (k < 5) ? w[c*20 + i*5 + k] : 0.f;
        ((float2*)wd)[idx] = make_float2(v, v);
    }
    __syncthreads();

    const int wrp = t >> 5, lane = t & 31;
    const int c0 = wrp*8, l0 = lane*8;

    ull A[8][4];
#pragma unroll
    for (int cc = 0; cc < 8; cc++){
        float cb = cbs[c0 + cc];
#pragma unroll
        for (int p = 0; p < 4; p++) A[cc][p] = pk(cb, cb);
    }
#pragma unroll
    for (int i = 0; i < 4; i++){
        const float* xb = xin + i*272 + l0;
        float4 u0 = *(const float4*)(xb);
        float4 u1 = *(const float4*)(xb + 4);
        float4 u2 = *(const float4*)(xb + 8);
        float xm[12] = {u0.x,u0.y,u0.z,u0.w, u1.x,u1.y,u1.z,u1.w, u2.x,u2.y,u2.z,u2.w};
        ull P[11];
#pragma unroll
        for (int m = 0; m < 11; m++) P[m] = pk(xm[m], xm[m+1]);
        const ull* wp = wd + (i*32 + c0)*8;
#pragma unroll
        for (int cc = 0; cc < 8; cc++){
            ulonglong2 W01 = *(const ulonglong2*)(wp + cc*8);
            ulonglong2 W23 = *(const ulonglong2*)(wp + cc*8 + 2);
            ull W4 = wp[cc*8 + 4];
#pragma unroll
            for (int p = 0; p < 4; p++){
                ffma2_acc(A[cc][p], P[2*p+0], W01.x);
                ffma2_acc(A[cc][p], P[2*p+1], W01.y);
                ffma2_acc(A[cc][p], P[2*p+2], W23.x);
                ffma2_acc(A[cc][p], P[2*p+3], W23.y);
                ffma2_acc(A[cc][p], P[2*p+4], W4);
            }
        }
    }

    float* outp = g_buf1 + (size_t)b*CH*LSEQ;
#pragma unroll
    for (int cc = 0; cc < 8; cc++){
        float v[8];
#pragma unroll
        for (int p = 0; p < 4; p++) upk(A[cc][p], v[2*p], v[2*p+1]);
        int c = c0 + cc;
        *(float4*)(outp + c*LSEQ + l0)     = make_float4(v[0],v[1],v[2],v[3]);
        *(float4*)(outp + c*LSEQ + l0 + 4) = make_float4(v[4],v[5],v[6],v[7]);
        float s = 0.f, q = 0.f;
#pragma unroll
        for (int m = 0; m < 8; m++){ s += v[m]; q += v[m]*v[m]; }
        s = wred32(s); q = wred32(q);
        if (lane == 0){ redS[c] = s; redQ[c] = q; }
    }
    __syncthreads();
    if (t < 32){
        atomicAdd(&g_stat[0][0][t], (double)redS[t]);
        atomicAdd(&g_stat[0][1][t], (double)redQ[t]);
    }
}

// ---------------- K2/K3: bn+relu -> conv(32->32,k3) via HMMA ---------------
// CTA = half sample (M=128 rows), 256 threads, warp w -> rows [w*16, w*16+16)
// Split-bf16: D = xh@wh + xl@wh + xh@wl  (fp32 accum)
__global__ __launch_bounds__(256, 3) void k_rbmma(int pass,
                                               const float* __restrict__ gam,
                                               const float* __restrict__ bet,
                                               const float* __restrict__ cbias){
    const int b = blockIdx.x >> 1;
    const int lbase = (blockIdx.x & 1) * 128;
    const int t = threadIdx.x;
    const int lane = t & 31, wrp = t >> 5;
    const float* bufIn = (pass == 0) ? g_buf1 : g_buf2;
    float* bufOut = (pass == 0) ? g_buf2 : g_buf3;
    const int stIn = pass, stOut = pass + 1;

    extern __shared__ char smc[];
    const uint32_t smb = smem_u32(smc);
    float* sc  = (float*)(smc + SMSC);
    float* sh  = sc + 32;
    float* cbs = sh + 32;
    float* redS= (float*)(smc + SMRED);
    float* redQ= redS + 256;

    // phase 0: BN constants + copy pre-converted B tiles (832 uint4)
    if (t < 32){
        const double N = (double)BATCH * (double)LSEQ;
        double S = g_stat[stIn][0][t], Q = g_stat[stIn][1][t];
        double m = S / N, v = Q / N - m*m;
        double s = (double)gam[t] / sqrt(v + EPSBN);
        sc[t] = (float)s;
        sh[t] = (float)((double)bet[t] - m*s);
        cbs[t] = cbias[t];
    }
    {
        const uint4* src = g_whl[pass];
        uint4* dst = (uint4*)(smc + SMWH);
        for (int i = t; i < 832; i += 256) dst[i] = src[i];
    }
    __syncthreads();

    // phase 1: bn+relu + direct im2col scatter (channel-major, coalesced LDG)
    {
        const float* inp = bufIn + (size_t)b*CH*LSEQ;
        for (int idx = t; idx < 32*130; idx += 256){
            int i = idx / 130, lp = idx - i*130;
            int l = lbase + lp - 1;
            float y = 0.f;
            if (l >= 0 && l < LSEQ) y = fmaxf(sc[i]*inp[i*LSEQ + l] + sh[i], 0.f);
            __nv_bfloat16 h = __float2bfloat16(y);
            __nv_bfloat16 lo = __float2bfloat16(y - __bfloat162float(h));
#pragma unroll
            for (int kk = 0; kk < 3; kk++){
                int p = lp - kk;
                if (p >= 0 && p < 128){
                    *(__nv_bfloat16*)(smc + SMA + (p*STRA + kk*32 + i)*2)      = h;
                    *(__nv_bfloat16*)(smc + SMA + (p*STRA + 96 + kk*32 + i)*2) = lo;
                }
            }
        }
    }
    __syncthreads();

    // mainloop: warp owns rows [m0, m0+16); 3 sub-GEMMs x 6 k16-steps
    const int m0 = wrp*16;
    float d[4][4];
#pragma unroll
    for (int tn = 0; tn < 4; tn++)
#pragma unroll
        for (int e = 0; e < 4; e++) d[tn][e] = 0.f;

    const uint32_t abase = smb + SMA +
        (uint32_t)(((m0 + (lane & 15))*STRA + ((lane & 16) ? 8 : 0)) * 2);
    const uint32_t bwh = smb + SMWH + (uint32_t)(((lane >> 2)*STRB + (lane & 3)*2) * 2);
    const uint32_t bwl = smb + SMWL + (uint32_t)(((lane >> 2)*STRB + (lane & 3)*2) * 2);

#pragma unroll
    for (int ks = 0; ks < 18; ks++){
        const int sub = ks / 6, kk = ks - sub*6;
        const uint32_t aaddr = abase + (uint32_t)(((sub == 1 ? 96 : 0) + kk*16) * 2);
        const uint32_t bb = (sub == 2 ? bwl : bwh) + (uint32_t)((kk*16) * 2);
        uint32_t a0,a1,a2,a3;
        LDMATRIX_X4(a0,a1,a2,a3, aaddr);
        uint32_t bf0[2], bf1[2], bf2[2], bf3[2];
        LDS32(bf0[0], bb);                 LDS32(bf0[1], bb + 16);
        LDS32(bf1[0], bb + 8*STRB*2);      LDS32(bf1[1], bb + 8*STRB*2 + 16);
        LDS32(bf2[0], bb + 16*STRB*2);     LDS32(bf2[1], bb + 16*STRB*2 + 16);
        LDS32(bf3[0], bb + 24*STRB*2);     LDS32(bf3[1], bb + 24*STRB*2 + 16);
        MMA16816(d[0], a0,a1,a2,a3, bf0[0], bf0[1]);
        MMA16816(d[1], a0,a1,a2,a3, bf1[0], bf1[1]);
        MMA16816(d[2], a0,a1,a2,a3, bf2[0], bf2[1]);
        MMA16816(d[3], a0,a1,a2,a3, bf3[0], bf3[1]);
    }

    // epilogue: bias, store, per-channel stats
    float* outp = bufOut + (size_t)b*CH*LSEQ + lbase;
    float ps[8], pq[8];
#pragma unroll
    for (int j = 0; j < 8; j++){ ps[j] = 0.f; pq[j] = 0.f; }
    {
        int r0 = m0 + (lane >> 2);
#pragma unroll
        for (int tn = 0; tn < 4; tn++){
            int c0 = tn*8 + (lane & 3)*2;
            float v00 = d[tn][0] + cbs[c0];
            float v01 = d[tn][1] + cbs[c0+1];
            float v10 = d[tn][2] + cbs[c0];
            float v11 = d[tn][3] + cbs[c0+1];
            outp[c0*LSEQ + r0]         = v00;
            outp[(c0+1)*LSEQ + r0]     = v01;
            outp[c0*LSEQ + r0 + 8]     = v10;
            outp[(c0+1)*LSEQ + r0 + 8] = v11;
            ps[tn*2+0] += v00 + v10;  pq[tn*2+0] += v00*v00 + v10*v10;
            ps[tn*2+1] += v01 + v11;  pq[tn*2+1] += v01*v01 + v11*v11;
        }
    }
#pragma unroll
    for (int j = 0; j < 8; j++){
#pragma unroll
        for (int o = 4; o < 32; o <<= 1){
            ps[j] += __shfl_xor_sync(0xffffffffu, ps[j], o);
            pq[j] += __shfl_xor_sync(0xffffffffu, pq[j], o);
        }
    }
    if (lane < 4){
#pragma unroll
        for (int tn = 0; tn < 4; tn++){
#pragma unroll
            for (int p = 0; p < 2; p++){
                int c = tn*8 + lane*2 + p;
                redS[wrp*32 + c] = ps[tn*2+p];
                redQ[wrp*32 + c] = pq[tn*2+p];
            }
        }
    }
    __syncthreads();
    if (t < 32){
        double S = 0.0, Q = 0.0;
#pragma unroll
        for (int wI = 0; wI < 8; wI++){ S += redS[wI*32 + t]; Q += redQ[wI*32 + t]; }
        atomicAdd(&g_stat[stOut][0][t], S);
        atomicAdd(&g_stat[stOut][1][t], Q);
    }
}

// ---------------- K4: bn0+relu, bn2, residual+relu, mean-pool, linear+tanh -
__global__ __launch_bounds__(256) void k_pool_ctx(const float* __restrict__ gamma1,
                                                  const float* __restrict__ beta1,
                                                  const float* __restrict__ gamma3,
                                                  const float* __restrict__ beta3,
                                                  const float* __restrict__ lin_w,
                                                  const float* __restrict__ lin_b){
    const int b = blockIdx.x;
    const int t = threadIdx.x;
    __shared__ float sc0[32], sh0[32], sc2[32], sh2[32];
    __shared__ float red[32][8];
    __shared__ float pooled[32];

    if (t < 32){
        const double N = (double)BATCH * (double)LSEQ;
        { double S = g_stat[0][0][t], Q = g_stat[0][1][t];
          double m = S/N, v = Q/N - m*m;
          double s = (double)gamma1[t] / sqrt(v + EPSBN);
          sc0[t] = (float)s; sh0[t] = (float)((double)beta1[t] - m*s); }
        { double S = g_stat[2][0][t], Q = g_stat[2][1][t];
          double m = S/N, v = Q/N - m*m;
          double s = (double)gamma3[t] / sqrt(v + EPSBN);
          sc2[t] = (float)s; sh2[t] = (float)((double)beta3[t] - m*s); }
    }
    __syncthreads();

    const float* p1 = g_buf1 + (size_t)b*CH*LSEQ;
    const float* p2 = g_buf3 + (size_t)b*CH*LSEQ;
    const int wid = t >> 5, lane = t & 31;
#pragma unroll 1
    for (int c = 0; c < 32; c++){
        float y1 = p1[c*LSEQ + t];
        float h2 = p2[c*LSEQ + t];
        float x1 = fmaxf(sc0[c]*y1 + sh0[c], 0.f);
        float x2 = fmaxf(sc2[c]*h2 + sh2[c] + x1, 0.f);
        float s = wred32(x2);
        if (lane == 0) red[c][wid] = s;
    }
    __syncthreads();
    if (t < 32){
        float s = 0.f;
#pragma unroll
        for (int wI = 0; wI < 8; wI++) s += red[t][wI];
        pooled[t] = s * (1.f/(float)LSEQ);
    }
    __syncthreads();
    if (t < 64){
        float acc = lin_b[t];
#pragma unroll
        for (int c = 0; c < 32; c++) acc += pooled[c]*lin_w[c*64 + t];
        g_ctx[(size_t)b*64 + t] = tanhf(acc);
    }
}

// ---------------- K5: 10 coupling layers, 64 rows per block, all in smem ---
__global__ __launch_bounds__(256) void k_coupling(const float* __restrict__ zin,
                                                  const float* __restrict__ W1,
                                                  const float* __restrict__ B1w,
                                                  const float* __restrict__ W2,
                                                  const float* __restrict__ B2w,
                                                  const float* __restrict__ W3,
                                                  const float* __restrict__ B3w,
                                                  float* __restrict__ outp){
    const int t = threadIdx.x;
    const int rowBase = blockIdx.x * 64;
    extern __shared__ float sm[];
    float* nin = sm;
    float* hA  = nin + 64*76;
    float* hB  = hA  + 64*132;
    float* zz  = hB  + 64*132;
    float* ob  = zz  + 64*12;
    float* ldv = ob  + 64*20;

    for (int idx = t; idx < 64*9; idx += 256){
        int r = idx/9, j = idx - r*9;
        zz[r*12 + j] = zin[(size_t)(rowBase + r)*9 + j];
    }
    for (int idx = t; idx < 64*64; idx += 256){
        int r = idx >> 6, j = idx & 63;
        nin[r*76 + 9 + j] = g_ctx[(size_t)(rowBase + r)*64 + j];
    }
    if (t < 64) ldv[t] = 0.f;
    __syncthreads();

    const int jc = t & 31;
    const int r0 = (t >> 5) * 8;

    for (int layer = 0; layer < 10; ++layer){
        if (t < 64){
#pragma unroll
            for (int j = 0; j < 9; j++){
                float m = (((j + layer) & 1) == 0) ? 1.f : 0.f;
                nin[t*76 + j] = zz[t*12 + j] * m;
            }
        }
        __syncthreads();
        {
            const float* Wl = W1 + (size_t)layer*73*128;
            float4 bb = *(const float4*)(B1w + layer*128 + 4*jc);
            ull acc[8][2];
#pragma unroll
            for (int r = 0; r < 8; r++){ acc[r][0] = pk(bb.x, bb.y); acc[r][1] = pk(bb.z, bb.w); }
#pragma unroll 2
            for (int i = 0; i < 73; i++){
                ulonglong2 wv = *(const ulonglong2*)(Wl + i*128 + 4*jc);
#pragma unroll
                for (int r = 0; r < 8; r++){
                    float x = nin[(r0 + r)*76 + i];
                    ull xx = pk(x, x);
                    ffma2_acc(acc[r][0], xx, wv.x);
                    ffma2_acc(acc[r][1], xx, wv.y);
                }
            }
#pragma unroll
            for (int r = 0; r < 8; r++){
                float v0,v1,v2,v3;
                upk(acc[r][0], v0, v1); upk(acc[r][1], v2, v3);
                *(float4*)(hA + (r0 + r)*132 + 4*jc) =
                    make_float4(fmaxf(v0,0.f), fmaxf(v1,0.f), fmaxf(v2,0.f), fmaxf(v3,0.f));
            }
        }
        __syncthreads();
        {
            const float* Wl = W2 + (size_t)layer*128*128;
            float4 bb = *(const float4*)(B2w + layer*128 + 4*jc);
            ull acc[8][2];
#pragma unroll
            for (int r = 0; r < 8; r++){ acc[r][0] = pk(bb.x, bb.y); acc[r][1] = pk(bb.z, bb.w); }
#pragma unroll 2
            for (int i = 0; i < 128; i++){
                ulonglong2 wv = *(const ulonglong2*)(Wl + i*128 + 4*jc);
#pragma unroll
                for (int r = 0; r < 8; r++){
                    float x = hA[(r0 + r)*132 + i];
                    ull xx = pk(x, x);
                    ffma2_acc(acc[r][0], xx, wv.x);
                    ffma2_acc(acc[r][1], xx, wv.y);
                }
            }
#pragma unroll
            for (int r = 0; r < 8; r++){
                float v0,v1,v2,v3;
                upk(acc[r][0], v0, v1); upk(acc[r][1], v2, v3);
                *(float4*)(hB + (r0 + r)*132 + 4*jc) =
                    make_float4(fmaxf(v0,0.f), fmaxf(v1,0.f), fmaxf(v2,0.f), fmaxf(v3,0.f));
            }
        }
        __syncthreads();
        {
            const float* Wl = W3 + (size_t)layer*128*18;
            const int r = t >> 2, q = t & 3;
            float acc[5] = {0.f,0.f,0.f,0.f,0.f};
#pragma unroll 2
            for (int i = 0; i < 128; i++){
                float x = hB[r*132 + i];
#pragma unroll
                for (int k = 0; k < 5; k++){
                    int j = q + 4*k;
                    if (j < 18) acc[k] = fmaf(x, __ldg(Wl + i*18 + j), acc[k]);
                }
            }
#pragma unroll
            for (int k = 0; k < 5; k++){
                int j = q + 4*k;
                if (j < 18) ob[r*20 + j] = acc[k] + B3w[layer*18 + j];
            }
        }
        __syncthreads();
        if (t < 64){
            float ldl = ldv[t];
#pragma unroll
            for (int j = 0; j < 9; j++){
                if (((j + layer) & 1) != 0){
                    float s  = tanhf(ob[t*20 + j]);
                    float tt = ob[t*20 + 9 + j];
                    zz[t*12 + j] = zz[t*12 + j]*expf(s) + tt;
                    ldl += s;
                }
            }
            ldv[t] = ldl;
        }
        __syncthreads();
    }

    if (t < 64){
        float lp = 0.f;
#pragma unroll
        for (int j = 0; j < 9; j++){
            float z = zz[t*12 + j];
            lp += LOG2PI + z*z;
        }
        outp[rowBase + t] = ldv[t] - 0.5f*lp;
    }
}

// ---------------- launch ----------------------------------------------------
extern "C" void kernel_launch(void* const* d_in, const int* in_sizes, int n_in,
                              void* d_out, int out_size){
    const float* inputs  = (const float*)d_in[0];
    const float* curve   = (const float*)d_in[1];
    const float* conv1_w = (const float*)d_in[2];
    const float* conv1_b = (const float*)d_in[3];
    const float* bn1_g   = (const float*)d_in[4];
    const float* bn1_b   = (const float*)d_in[5];
    const float* rb_w1   = (const float*)d_in[6];
    const float* rb_b1   = (const float*)d_in[7];
    const float* rb_g1   = (const float*)d_in[8];
    const float* rb_be1  = (const float*)d_in[9];
    const float* rb_w2   = (const float*)d_in[10];
    const float* rb_b2   = (const float*)d_in[11];
    const float* rb_g2   = (const float*)d_in[12];
    const float* rb_be2  = (const float*)d_in[13];
    const float* lin_w   = (const float*)d_in[14];
    const float* lin_b   = (const float*)d_in[15];
    const float* W1      = (const float*)d_in[16];
    const float* B1      = (const float*)d_in[17];
    const float* W2      = (const float*)d_in[18];
    const float* B2      = (const float*)d_in[19];
    const float* W3      = (const float*)d_in[20];
    const float* B3      = (const float*)d_in[21];
    float* out = (float*)d_out;

    const int smem1 = 1024*8 + (32 + 4*272 + 32 + 32) * 4;
    const int smemC = (64*76 + 64*132*2 + 64*12 + 64*20 + 64) * 4;

    cudaFuncSetAttribute(k_conv1,    cudaFuncAttributeMaxDynamicSharedMemorySize, smem1);
    cudaFuncSetAttribute(k_rbmma,    cudaFuncAttributeMaxDynamicSharedMemorySize, SM_TOTAL_M);
    cudaFuncSetAttribute(k_coupling, cudaFuncAttributeMaxDynamicSharedMemorySize, smemC);

    k_prep<<<1, 256>>>(rb_w1, rb_w2);
    k_conv1<<<BATCH, 128, smem1>>>(curve, conv1_w, conv1_b);
    k_rbmma<<<BATCH*2, 256, SM_TOTAL_M>>>(0, bn1_g, bn1_b, rb_b1);
    k_rbmma<<<BATCH*2, 256, SM_TOTAL_M>>>(1, rb_g1, rb_be1, rb_b2);
    k_pool_ctx<<<BATCH, 256>>>(bn1_g, bn1_b, rb_g2, rb_be2, lin_w, lin_b);
    k_coupling<<<BATCH/64, 256, smemC>>>(inputs, W1, B1, W2, B2, W3, B3, out);
}

// round 10
// speedup vs baseline: 1.6205x; 1.2990x over previous
#include <cuda_runtime.h>
#include <cuda_bf16.h>
#include <cstdint>

#define BATCH 16384
#define LSEQ  256
#define CH    32
#define EPSBN 1e-5
#define LOG2PI 1.8378770664093453f

typedef unsigned long long ull;

// ---------------- scratch (device-global; no runtime alloc allowed) -------
__device__ float  g_buf1[(size_t)BATCH*CH*LSEQ];   // conv1 output (pre-BN)
__device__ float  g_buf2[(size_t)BATCH*CH*LSEQ];   // h1 (pre-BN)
__device__ float  g_buf3[(size_t)BATCH*CH*LSEQ];   // h2 (pre-BN)
__device__ float  g_ctx [(size_t)BATCH*64];        // context vectors
__device__ double g_stat[3][2][32];                // [stage][sum|sumsq][channel]
__device__ uint2  g_frag[2][2][768];               // [pass][wh|wl][(ks6*4+tn)*32+lane]

// ---------------- packed fp32x2 helpers (FFMA2, conv1/coupling) ------------
__device__ __forceinline__ ull pk(float lo, float hi){
    ull r; asm("mov.b64 %0, {%1,%2};" : "=l"(r) : "f"(lo), "f"(hi)); return r;
}
__device__ __forceinline__ void upk(ull v, float& lo, float& hi){
    asm("mov.b64 {%0,%1}, %2;" : "=f"(lo), "=f"(hi) : "l"(v));
}
__device__ __forceinline__ void ffma2_acc(ull& a, ull b, ull c){
    asm("fma.rn.f32x2 %0, %1, %2, %0;" : "+l"(a) : "l"(b), "l"(c));
}
__device__ __forceinline__ float wred32(float v){
#pragma unroll
    for (int o = 16; o > 0; o >>= 1) v += __shfl_xor_sync(0xffffffffu, v, o);
    return v;
}
__device__ __forceinline__ uint32_t smem_u32(const void* p){
    uint32_t a;
    asm("{ .reg .u64 t; cvta.to.shared.u64 t, %1; cvt.u32.u64 %0, t; }" : "=r"(a) : "l"(p));
    return a;
}

// ---------------- warp-MMA helpers (baseline PTX, works on sm_103) --------
#define LDMATRIX_X4(a0,a1,a2,a3, addr) \
    asm volatile("ldmatrix.sync.aligned.m8n8.x4.shared.b16 {%0,%1,%2,%3}, [%4];" \
        : "=r"(a0), "=r"(a1), "=r"(a2), "=r"(a3) : "r"(addr))
#define LDS64V(x0,x1, addr) \
    asm volatile("ld.shared.v2.u32 {%0,%1}, [%2];" : "=r"(x0), "=r"(x1) : "r"(addr))
#define MMA16816(d, a0,a1,a2,a3, b0,b1) \
    asm volatile("mma.sync.aligned.m16n8k16.row.col.f32.bf16.bf16.f32 " \
        "{%0,%1,%2,%3}, {%4,%5,%6,%7}, {%8,%9}, {%0,%1,%2,%3};" \
        : "+f"((d)[0]), "+f"((d)[1]), "+f"((d)[2]), "+f"((d)[3]) \
        : "r"(a0), "r"(a1), "r"(a2), "r"(a3), "r"(b0), "r"(b1))

// x buffer: 131 rows x 144 bytes (32 xh bf16 | 32 xl bf16, 16B pad)
#define STRXB 144
// smem byte offsets for k_rbmma
#define SMX    0            // 131*144 = 18864
#define SMWHF  18864        // 768 uint2 = 6144
#define SMWLF  25008        // 6144
#define SMSC   31152        // sc[32], sh[32], cbs[32] = 384
#define SMRED  31536        // redS[8][32], redQ[8][32] = 2048
#define SM_TOTAL_M 33584

// ---------------- K0: zero stats + pre-pack B fragments --------------------
__global__ void k_prep(const float* __restrict__ w1, const float* __restrict__ w2){
    const int t = threadIdx.x;
    if (t < 192) (&g_stat[0][0][0])[t] = 0.0;
#pragma unroll 1
    for (int pass = 0; pass < 2; pass++){
        const float* w = pass ? w2 : w1;
        for (int idx = t; idx < 768; idx += 256){
            int ks6 = idx >> 7, rem = idx & 127, tn = rem >> 5, lane = rem & 31;
            int n = tn*8 + (lane >> 2);
            int kb = ks6*16 + (lane & 3)*2;
            float v[4];
#pragma unroll
            for (int e = 0; e < 4; e++){
                int k = kb + (e >> 1)*8 + (e & 1);      // kb, kb+1, kb+8, kb+9
                int i = k & 31, kkb = k >> 5;
                v[e] = w[n*96 + i*3 + kkb];
            }
            uint32_t h0, h1, l0, l1;
            float hh[4], ll[4];
#pragma unroll
            for (int e = 0; e < 4; e++){
                __nv_bfloat16 h = __float2bfloat16(v[e]);
                hh[e] = __bfloat162float(h);
                ll[e] = v[e] - hh[e];
            }
            asm("cvt.rn.bf16x2.f32 %0, %1, %2;" : "=r"(h0) : "f"(hh[1]), "f"(hh[0]));
            asm("cvt.rn.bf16x2.f32 %0, %1, %2;" : "=r"(h1) : "f"(hh[3]), "f"(hh[2]));
            asm("cvt.rn.bf16x2.f32 %0, %1, %2;" : "=r"(l0) : "f"(ll[1]), "f"(ll[0]));
            asm("cvt.rn.bf16x2.f32 %0, %1, %2;" : "=r"(l1) : "f"(ll[3]), "f"(ll[2]));
            g_frag[pass][0][idx] = make_uint2(h0, h1);
            g_frag[pass][1][idx] = make_uint2(l0, l1);
        }
    }
}

// ---------------- K1: conv1 (4->32, k=5, SAME) + bias, stats stage 0 -------
__global__ __launch_bounds__(128) void k_conv1(const float* __restrict__ curve,
                                               const float* __restrict__ w,
                                               const float* __restrict__ bias){
    const int b = blockIdx.x;
    const int t = threadIdx.x;
    extern __shared__ ull smu[];
    ull*   wd  = smu;                     // dup weights: ull[(i*32+c)*8 + k], 1024
    float* cbs = (float*)(wd + 1024);
    float* xin = cbs + 32;                // 4*272
    float* redS= xin + 4*272;
    float* redQ= redS + 32;

    if (t < 32) cbs[t] = bias[t];
    for (int idx = t; idx < 4*272; idx += 128){
        int i = idx / 272, p = idx - i*272, l = p - 2;
        xin[idx] = (l >= 0 && l < LSEQ) ? curve[((size_t)b*4 + i)*LSEQ + l] : 0.f;
    }
    for (int idx = t; idx < 4*32*8; idx += 128){
        int i = idx >> 8, rem = idx & 255, c = rem >> 3, k = rem & 7;
        float v = (k < 5) ? w[c*20 + i*5 + k] : 0.f;
        ((float2*)wd)[idx] = make_float2(v, v);
    }
    __syncthreads();

    const int wrp = t >> 5, lane = t & 31;
    const int c0 = wrp*8, l0 = lane*8;

    ull A[8][4];
#pragma unroll
    for (int cc = 0; cc < 8; cc++){
        float cb = cbs[c0 + cc];
#pragma unroll
        for (int p = 0; p < 4; p++) A[cc][p] = pk(cb, cb);
    }
#pragma unroll
    for (int i = 0; i < 4; i++){
        const float* xb = xin + i*272 + l0;
        float4 u0 = *(const float4*)(xb);
        float4 u1 = *(const float4*)(xb + 4);
        float4 u2 = *(const float4*)(xb + 8);
        float xm[12] = {u0.x,u0.y,u0.z,u0.w, u1.x,u1.y,u1.z,u1.w, u2.x,u2.y,u2.z,u2.w};
        ull P[11];
#pragma unroll
        for (int m = 0; m < 11; m++) P[m] = pk(xm[m], xm[m+1]);
        const ull* wp = wd + (i*32 + c0)*8;
#pragma unroll
        for (int cc = 0; cc < 8; cc++){
            ulonglong2 W01 = *(const ulonglong2*)(wp + cc*8);
            ulonglong2 W23 = *(const ulonglong2*)(wp + cc*8 + 2);
            ull W4 = wp[cc*8 + 4];
#pragma unroll
            for (int p = 0; p < 4; p++){
                ffma2_acc(A[cc][p], P[2*p+0], W01.x);
                ffma2_acc(A[cc][p], P[2*p+1], W01.y);
                ffma2_acc(A[cc][p], P[2*p+2], W23.x);
                ffma2_acc(A[cc][p], P[2*p+3], W23.y);
                ffma2_acc(A[cc][p], P[2*p+4], W4);
            }
        }
    }

    float* outp = g_buf1 + (size_t)b*CH*LSEQ;
#pragma unroll
    for (int cc = 0; cc < 8; cc++){
        float v[8];
#pragma unroll
        for (int p = 0; p < 4; p++) upk(A[cc][p], v[2*p], v[2*p+1]);
        int c = c0 + cc;
        *(float4*)(outp + c*LSEQ + l0)     = make_float4(v[0],v[1],v[2],v[3]);
        *(float4*)(outp + c*LSEQ + l0 + 4) = make_float4(v[4],v[5],v[6],v[7]);
        float s = 0.f, q = 0.f;
#pragma unroll
        for (int m = 0; m < 8; m++){ s += v[m]; q += v[m]*v[m]; }
        s = wred32(s); q = wred32(q);
        if (lane == 0){ redS[c] = s; redQ[c] = q; }
    }
    __syncthreads();
    if (t < 32){
        atomicAdd(&g_stat[0][0][t], (double)redS[t]);
        atomicAdd(&g_stat[0][1][t], (double)redQ[t]);
    }
}

// ---------------- K2/K3: bn+relu -> conv(32->32,k3) via HMMA ---------------
// CTA = half sample (M=128 rows). No im2col: A K-blocks are row-shifted views
// of one x buffer; shift realized in ldmatrix base address.
// Split-bf16: D = xh@wh + xl@wh + xh@wl (fp32 accum)
__global__ __launch_bounds__(256, 4) void k_rbmma(int pass,
                                               const float* __restrict__ gam,
                                               const float* __restrict__ bet,
                                               const float* __restrict__ cbias){
    const int b = blockIdx.x >> 1;
    const int lbase = (blockIdx.x & 1) * 128;
    const int t = threadIdx.x;
    const int lane = t & 31, wrp = t >> 5;
    const float* bufIn = (pass == 0) ? g_buf1 : g_buf2;
    float* bufOut = (pass == 0) ? g_buf2 : g_buf3;
    const int stIn = pass, stOut = pass + 1;

    extern __shared__ char smc[];
    const uint32_t smb = smem_u32(smc);
    float* sc  = (float*)(smc + SMSC);
    float* sh  = sc + 32;
    float* cbs = sh + 32;
    float* redS= (float*)(smc + SMRED);
    float* redQ= redS + 256;

    // phase 0: BN constants + copy pre-packed B fragments (1536 uint2)
    if (t < 32){
        const double N = (double)BATCH * (double)LSEQ;
        double S = g_stat[stIn][0][t], Q = g_stat[stIn][1][t];
        double m = S / N, v = Q / N - m*m;
        double s = (double)gam[t] / sqrt(v + EPSBN);
        sc[t] = (float)s;
        sh[t] = (float)((double)bet[t] - m*s);
        cbs[t] = cbias[t];
    }
    {
        const uint4* src = (const uint4*)&g_frag[pass][0][0];
        uint4* dst = (uint4*)(smc + SMWHF);
#pragma unroll
        for (int i = 0; i < 3; i++) dst[t + i*256] = src[t + i*256];
    }
    __syncthreads();

    // phase 1: bn+relu -> x buffer, one write per (row, channel-pair)
    {
        const float* inp = bufIn + (size_t)b*CH*LSEQ;
        for (int idx = t; idx < 16*130; idx += 256){
            int ip = idx / 130, lp = idx - ip*130;
            int i = ip*2;
            int l = lbase + lp - 1;
            float y0 = 0.f, y1 = 0.f;
            if (l >= 0 && l < LSEQ){
                y0 = fmaxf(sc[i]*inp[i*LSEQ + l] + sh[i], 0.f);
                y1 = fmaxf(sc[i+1]*inp[(i+1)*LSEQ + l] + sh[i+1], 0.f);
            }
            uint32_t hp;
            asm("cvt.rn.bf16x2.f32 %0, %1, %2;" : "=r"(hp) : "f"(y1), "f"(y0));
            float h0 = __uint_as_float(hp << 16);
            float h1 = __uint_as_float(hp & 0xffff0000u);
            float e0 = y0 - h0, e1 = y1 - h1;
            uint32_t lp2;
            asm("cvt.rn.bf16x2.f32 %0, %1, %2;" : "=r"(lp2) : "f"(e1), "f"(e0));
            *(uint32_t*)(smc + SMX + lp*STRXB + i*2)      = hp;
            *(uint32_t*)(smc + SMX + lp*STRXB + 64 + i*2) = lp2;
        }
    }
    __syncthreads();

    // mainloop: warp owns rows [m0, m0+16); 3 sub-GEMMs x 6 k16-steps
    const int m0 = wrp*16;
    float d[4][4];
#pragma unroll
    for (int tn = 0; tn < 4; tn++)
#pragma unroll
        for (int e = 0; e < 4; e++) d[tn][e] = 0.f;

    const uint32_t axbase = smb + SMX +
        (uint32_t)((m0 + (lane & 15))*STRXB + ((lane & 16) ? 16 : 0));
    const uint32_t bwh = smb + SMWHF + (uint32_t)(lane*8);
    const uint32_t bwl = smb + SMWLF + (uint32_t)(lane*8);

#pragma unroll
    for (int sub = 0; sub < 3; sub++){
        const uint32_t acol  = (sub == 1) ? 64u : 0u;
        const uint32_t btile = (sub == 2) ? bwl : bwh;
#pragma unroll
        for (int ks6 = 0; ks6 < 6; ks6++){
            const int kk = ks6 >> 1, kc = ks6 & 1;
            uint32_t a0,a1,a2,a3;
            LDMATRIX_X4(a0,a1,a2,a3, axbase + (uint32_t)(kk*STRXB + kc*32) + acol);
            uint32_t b00,b01,b10,b11,b20,b21,b30,b31;
            LDS64V(b00,b01, btile + (uint32_t)((ks6*4 + 0)*256));
            LDS64V(b10,b11, btile + (uint32_t)((ks6*4 + 1)*256));
            LDS64V(b20,b21, btile + (uint32_t)((ks6*4 + 2)*256));
            LDS64V(b30,b31, btile + (uint32_t)((ks6*4 + 3)*256));
            MMA16816(d[0], a0,a1,a2,a3, b00,b01);
            MMA16816(d[1], a0,a1,a2,a3, b10,b11);
            MMA16816(d[2], a0,a1,a2,a3, b20,b21);
            MMA16816(d[3], a0,a1,a2,a3, b30,b31);
        }
    }

    // epilogue: bias, store (32B-sector chunks), per-channel stats
    float* outp = bufOut + (size_t)b*CH*LSEQ + lbase;
    float ps[8], pq[8];
#pragma unroll
    for (int j = 0; j < 8; j++){ ps[j] = 0.f; pq[j] = 0.f; }
    {
        int r0 = m0 + (lane >> 2);
#pragma unroll
        for (int tn = 0; tn < 4; tn++){
            int c0 = tn*8 + (lane & 3)*2;
            float v00 = d[tn][0] + cbs[c0];
            float v01 = d[tn][1] + cbs[c0+1];
            float v10 = d[tn][2] + cbs[c0];
            float v11 = d[tn][3] + cbs[c0+1];
            outp[c0*LSEQ + r0]         = v00;
            outp[(c0+1)*LSEQ + r0]     = v01;
            outp[c0*LSEQ + r0 + 8]     = v10;
            outp[(c0+1)*LSEQ + r0 + 8] = v11;
            ps[tn*2+0] += v00 + v10;  pq[tn*2+0] += v00*v00 + v10*v10;
            ps[tn*2+1] += v01 + v11;  pq[tn*2+1] += v01*v01 + v11*v11;
        }
    }
#pragma unroll
    for (int j = 0; j < 8; j++){
#pragma unroll
        for (int o = 4; o < 32; o <<= 1){
            ps[j] += __shfl_xor_sync(0xffffffffu, ps[j], o);
            pq[j] += __shfl_xor_sync(0xffffffffu, pq[j], o);
        }
    }
    if (lane < 4){
#pragma unroll
        for (int tn = 0; tn < 4; tn++){
#pragma unroll
            for (int p = 0; p < 2; p++){
                int c = tn*8 + lane*2 + p;
                redS[wrp*32 + c] = ps[tn*2+p];
                redQ[wrp*32 + c] = pq[tn*2+p];
            }
        }
    }
    __syncthreads();
    if (t < 32){
        double S = 0.0, Q = 0.0;
#pragma unroll
        for (int wI = 0; wI < 8; wI++){ S += redS[wI*32 + t]; Q += redQ[wI*32 + t]; }
        atomicAdd(&g_stat[stOut][0][t], S);
        atomicAdd(&g_stat[stOut][1][t], Q);
    }
}

// ---------------- K4: bn0+relu, bn2, residual+relu, mean-pool, linear+tanh -
__global__ __launch_bounds__(256) void k_pool_ctx(const float* __restrict__ gamma1,
                                                  const float* __restrict__ beta1,
                                                  const float* __restrict__ gamma3,
                                                  const float* __restrict__ beta3,
                                                  const float* __restrict__ lin_w,
                                                  const float* __restrict__ lin_b){
    const int b = blockIdx.x;
    const int t = threadIdx.x;
    __shared__ float sc0[32], sh0[32], sc2[32], sh2[32];
    __shared__ float red[32][8];
    __shared__ float pooled[32];

    if (t < 32){
        const double N = (double)BATCH * (double)LSEQ;
        { double S = g_stat[0][0][t], Q = g_stat[0][1][t];
          double m = S/N, v = Q/N - m*m;
          double s = (double)gamma1[t] / sqrt(v + EPSBN);
          sc0[t] = (float)s; sh0[t] = (float)((double)beta1[t] - m*s); }
        { double S = g_stat[2][0][t], Q = g_stat[2][1][t];
          double m = S/N, v = Q/N - m*m;
          double s = (double)gamma3[t] / sqrt(v + EPSBN);
          sc2[t] = (float)s; sh2[t] = (float)((double)beta3[t] - m*s); }
    }
    __syncthreads();

    const float* p1 = g_buf1 + (size_t)b*CH*LSEQ;
    const float* p2 = g_buf3 + (size_t)b*CH*LSEQ;
    const int wid = t >> 5, lane = t & 31;
#pragma unroll 1
    for (int c = 0; c < 32; c++){
        float y1 = p1[c*LSEQ + t];
        float h2 = p2[c*LSEQ + t];
        float x1 = fmaxf(sc0[c]*y1 + sh0[c], 0.f);
        float x2 = fmaxf(sc2[c]*h2 + sh2[c] + x1, 0.f);
        float s = wred32(x2);
        if (lane == 0) red[c][wid] = s;
    }
    __syncthreads();
    if (t < 32){
        float s = 0.f;
#pragma unroll
        for (int wI = 0; wI < 8; wI++) s += red[t][wI];
        pooled[t] = s * (1.f/(float)LSEQ);
    }
    __syncthreads();
    if (t < 64){
        float acc = lin_b[t];
#pragma unroll
        for (int c = 0; c < 32; c++) acc += pooled[c]*lin_w[c*64 + t];
        g_ctx[(size_t)b*64 + t] = tanhf(acc);
    }
}

// ---------------- K5: 10 coupling layers, 64 rows per block, all in smem ---
__global__ __launch_bounds__(256) void k_coupling(const float* __restrict__ zin,
                                                  const float* __restrict__ W1,
                                                  const float* __restrict__ B1w,
                                                  const float* __restrict__ W2,
                                                  const float* __restrict__ B2w,
                                                  const float* __restrict__ W3,
                                                  const float* __restrict__ B3w,
                                                  float* __restrict__ outp){
    const int t = threadIdx.x;
    const int rowBase = blockIdx.x * 64;
    extern __shared__ float sm[];
    float* nin = sm;
    float* hA  = nin + 64*76;
    float* hB  = hA  + 64*132;
    float* zz  = hB  + 64*132;
    float* ob  = zz  + 64*12;
    float* ldv = ob  + 64*20;

    for (int idx = t; idx < 64*9; idx += 256){
        int r = idx/9, j = idx - r*9;
        zz[r*12 + j] = zin[(size_t)(rowBase + r)*9 + j];
    }
    for (int idx = t; idx < 64*64; idx += 256){
        int r = idx >> 6, j = idx & 63;
        nin[r*76 + 9 + j] = g_ctx[(size_t)(rowBase + r)*64 + j];
    }
    if (t < 64) ldv[t] = 0.f;
    __syncthreads();

    const int jc = t & 31;
    const int r0 = (t >> 5) * 8;

    for (int layer = 0; layer < 10; ++layer){
        if (t < 64){
#pragma unroll
            for (int j = 0; j < 9; j++){
                float m = (((j + layer) & 1) == 0) ? 1.f : 0.f;
                nin[t*76 + j] = zz[t*12 + j] * m;
            }
        }
        __syncthreads();
        {
            const float* Wl = W1 + (size_t)layer*73*128;
            float4 bb = *(const float4*)(B1w + layer*128 + 4*jc);
            ull acc[8][2];
#pragma unroll
            for (int r = 0; r < 8; r++){ acc[r][0] = pk(bb.x, bb.y); acc[r][1] = pk(bb.z, bb.w); }
#pragma unroll 2
            for (int i = 0; i < 73; i++){
                ulonglong2 wv = *(const ulonglong2*)(Wl + i*128 + 4*jc);
#pragma unroll
                for (int r = 0; r < 8; r++){
                    float x = nin[(r0 + r)*76 + i];
                    ull xx = pk(x, x);
                    ffma2_acc(acc[r][0], xx, wv.x);
                    ffma2_acc(acc[r][1], xx, wv.y);
                }
            }
#pragma unroll
            for (int r = 0; r < 8; r++){
                float v0,v1,v2,v3;
                upk(acc[r][0], v0, v1); upk(acc[r][1], v2, v3);
                *(float4*)(hA + (r0 + r)*132 + 4*jc) =
                    make_float4(fmaxf(v0,0.f), fmaxf(v1,0.f), fmaxf(v2,0.f), fmaxf(v3,0.f));
            }
        }
        __syncthreads();
        {
            const float* Wl = W2 + (size_t)layer*128*128;
            float4 bb = *(const float4*)(B2w + layer*128 + 4*jc);
            ull acc[8][2];
#pragma unroll
            for (int r = 0; r < 8; r++){ acc[r][0] = pk(bb.x, bb.y); acc[r][1] = pk(bb.z, bb.w); }
#pragma unroll 2
            for (int i = 0; i < 128; i++){
                ulonglong2 wv = *(const ulonglong2*)(Wl + i*128 + 4*jc);
#pragma unroll
                for (int r = 0; r < 8; r++){
                    float x = hA[(r0 + r)*132 + i];
                    ull xx = pk(x, x);
                    ffma2_acc(acc[r][0], xx, wv.x);
                    ffma2_acc(acc[r][1], xx, wv.y);
                }
            }
#pragma unroll
            for (int r = 0; r < 8; r++){
                float v0,v1,v2,v3;
                upk(acc[r][0], v0, v1); upk(acc[r][1], v2, v3);
                *(float4*)(hB + (r0 + r)*132 + 4*jc) =
                    make_float4(fmaxf(v0,0.f), fmaxf(v1,0.f), fmaxf(v2,0.f), fmaxf(v3,0.f));
            }
        }
        __syncthreads();
        {
            const float* Wl = W3 + (size_t)layer*128*18;
            const int r = t >> 2, q = t & 3;
            float acc[5] = {0.f,0.f,0.f,0.f,0.f};
#pragma unroll 2
            for (int i = 0; i < 128; i++){
                float x = hB[r*132 + i];
#pragma unroll
                for (int k = 0; k < 5; k++){
                    int j = q + 4*k;
                    if (j < 18) acc[k] = fmaf(x, __ldg(Wl + i*18 + j), acc[k]);
                }
            }
#pragma unroll
            for (int k = 0; k < 5; k++){
                int j = q + 4*k;
                if (j < 18) ob[r*20 + j] = acc[k] + B3w[layer*18 + j];
            }
        }
        __syncthreads();
        if (t < 64){
            float ldl = ldv[t];
#pragma unroll
            for (int j = 0; j < 9; j++){
                if (((j + layer) & 1) != 0){
                    float s  = tanhf(ob[t*20 + j]);
                    float tt = ob[t*20 + 9 + j];
                    zz[t*12 + j] = zz[t*12 + j]*expf(s) + tt;
                    ldl += s;
                }
            }
            ldv[t] = ldl;
        }
        __syncthreads();
    }

    if (t < 64){
        float lp = 0.f;
#pragma unroll
        for (int j = 0; j < 9; j++){
            float z = zz[t*12 + j];
            lp += LOG2PI + z*z;
        }
        outp[rowBase + t] = ldv[t] - 0.5f*lp;
    }
}

// ---------------- launch ----------------------------------------------------
extern "C" void kernel_launch(void* const* d_in, const int* in_sizes, int n_in,
                              void* d_out, int out_size){
    const float* inputs  = (const float*)d_in[0];
    const float* curve   = (const float*)d_in[1];
    const float* conv1_w = (const float*)d_in[2];
    const float* conv1_b = (const float*)d_in[3];
    const float* bn1_g   = (const float*)d_in[4];
    const float* bn1_b   = (const float*)d_in[5];
    const float* rb_w1   = (const float*)d_in[6];
    const float* rb_b1   = (const float*)d_in[7];
    const float* rb_g1   = (const float*)d_in[8];
    const float* rb_be1  = (const float*)d_in[9];
    const float* rb_w2   = (const float*)d_in[10];
    const float* rb_b2   = (const float*)d_in[11];
    const float* rb_g2   = (const float*)d_in[12];
    const float* rb_be2  = (const float*)d_in[13];
    const float* lin_w   = (const float*)d_in[14];
    const float* lin_b   = (const float*)d_in[15];
    const float* W1      = (const float*)d_in[16];
    const float* B1      = (const float*)d_in[17];
    const float* W2      = (const float*)d_in[18];
    const float* B2      = (const float*)d_in[19];
    const float* W3      = (const float*)d_in[20];
    const float* B3      = (const float*)d_in[21];
    float* out = (float*)d_out;

    const int smem1 = 1024*8 + (32 + 4*272 + 32 + 32) * 4;
    const int smemC = (64*76 + 64*132*2 + 64*12 + 64*20 + 64) * 4;

    cudaFuncSetAttribute(k_conv1,    cudaFuncAttributeMaxDynamicSharedMemorySize, smem1);
    cudaFuncSetAttribute(k_rbmma,    cudaFuncAttributeMaxDynamicSharedMemorySize, SM_TOTAL_M);
    cudaFuncSetAttribute(k_coupling, cudaFuncAttributeMaxDynamicSharedMemorySize, smemC);

    k_prep<<<1, 256>>>(rb_w1, rb_w2);
    k_conv1<<<BATCH, 128, smem1>>>(curve, conv1_w, conv1_b);
    k_rbmma<<<BATCH*2, 256, SM_TOTAL_M>>>(0, bn1_g, bn1_b, rb_b1);
    k_rbmma<<<BATCH*2, 256, SM_TOTAL_M>>>(1, rb_g1, rb_be1, rb_b2);
    k_pool_ctx<<<BATCH, 256>>>(bn1_g, bn1_b, rb_g2, rb_be2, lin_w, lin_b);
    k_coupling<<<BATCH/64, 256, smemC>>>(inputs, W1, B1, W2, B2, W3, B3, out);
}

// round 11
// speedup vs baseline: 1.7657x; 1.0896x over previous
#include <cuda_runtime.h>
#include <cuda_bf16.h>
#include <cstdint>

#define BATCH 16384
#define LSEQ  256
#define CH    32
#define EPSBN 1e-5
#define LOG2PI 1.8378770664093453f

typedef unsigned long long ull;

// ---------------- scratch (device-global; no runtime alloc allowed) -------
__device__ float  g_buf1[(size_t)BATCH*CH*LSEQ];   // conv1 output (pre-BN)
__device__ float  g_buf2[(size_t)BATCH*CH*LSEQ];   // h1 (pre-BN)
__device__ float  g_buf3[(size_t)BATCH*CH*LSEQ];   // h2 (pre-BN)
__device__ float  g_ctx [(size_t)BATCH*64];        // context vectors
__device__ double g_stat[3][2][32];                // [stage][sum|sumsq][channel]
__device__ uint2  g_frag[2][2][768];               // [pass][wh|wl][(ks6*4+tn)*32+lane]

// ---------------- packed fp32x2 helpers (FFMA2, conv1/coupling) ------------
__device__ __forceinline__ ull pk(float lo, float hi){
    ull r; asm("mov.b64 %0, {%1,%2};" : "=l"(r) : "f"(lo), "f"(hi)); return r;
}
__device__ __forceinline__ void upk(ull v, float& lo, float& hi){
    asm("mov.b64 {%0,%1}, %2;" : "=f"(lo), "=f"(hi) : "l"(v));
}
__device__ __forceinline__ void ffma2_acc(ull& a, ull b, ull c){
    asm("fma.rn.f32x2 %0, %1, %2, %0;" : "+l"(a) : "l"(b), "l"(c));
}
__device__ __forceinline__ float wred32(float v){
#pragma unroll
    for (int o = 16; o > 0; o >>= 1) v += __shfl_xor_sync(0xffffffffu, v, o);
    return v;
}
__device__ __forceinline__ uint32_t smem_u32(const void* p){
    uint32_t a;
    asm("{ .reg .u64 t; cvta.to.shared.u64 t, %1; cvt.u32.u64 %0, t; }" : "=r"(a) : "l"(p));
    return a;
}

// ---------------- warp-MMA helpers (baseline PTX, works on sm_103) --------
#define LDMATRIX_X4(a0,a1,a2,a3, addr) \
    asm volatile("ldmatrix.sync.aligned.m8n8.x4.shared.b16 {%0,%1,%2,%3}, [%4];" \
        : "=r"(a0), "=r"(a1), "=r"(a2), "=r"(a3) : "r"(addr))
#define LDS64V(x0,x1, addr) \
    asm volatile("ld.shared.v2.u32 {%0,%1}, [%2];" : "=r"(x0), "=r"(x1) : "r"(addr))
#define MMA16816(d, a0,a1,a2,a3, b0,b1) \
    asm volatile("mma.sync.aligned.m16n8k16.row.col.f32.bf16.bf16.f32 " \
        "{%0,%1,%2,%3}, {%4,%5,%6,%7}, {%8,%9}, {%0,%1,%2,%3};" \
        : "+f"((d)[0]), "+f"((d)[1]), "+f"((d)[2]), "+f"((d)[3]) \
        : "r"(a0), "r"(a1), "r"(a2), "r"(a3), "r"(b0), "r"(b1))

// x buffer: 131 rows x 144 bytes (32 xh bf16 | 32 xl bf16, 16B pad)
#define STRXB 144
// smem byte offsets for k_rbmma
#define SMX    0            // 131*144 = 18864
#define SMWHF  18864        // 768 uint2 = 6144
#define SMWLF  25008        // 6144
#define SMSC   31152        // sc[32], sh[32], cbs[32] = 384
#define SMRED  31536        // redS[8][32], redQ[8][32] = 2048
#define SM_TOTAL_M 33584

// ---------------- K0: zero stats + pre-pack B fragments --------------------
__global__ void k_prep(const float* __restrict__ w1, const float* __restrict__ w2){
    const int t = threadIdx.x;
    if (t < 192) (&g_stat[0][0][0])[t] = 0.0;
#pragma unroll 1
    for (int pass = 0; pass < 2; pass++){
        const float* w = pass ? w2 : w1;
        for (int idx = t; idx < 768; idx += 256){
            int ks6 = idx >> 7, rem = idx & 127, tn = rem >> 5, lane = rem & 31;
            int n = tn*8 + (lane >> 2);
            int kb = ks6*16 + (lane & 3)*2;
            float v[4];
#pragma unroll
            for (int e = 0; e < 4; e++){
                int k = kb + (e >> 1)*8 + (e & 1);      // kb, kb+1, kb+8, kb+9
                int i = k & 31, kkb = k >> 5;
                v[e] = w[n*96 + i*3 + kkb];
            }
            uint32_t h0, h1, l0, l1;
            float hh[4], ll[4];
#pragma unroll
            for (int e = 0; e < 4; e++){
                __nv_bfloat16 h = __float2bfloat16(v[e]);
                hh[e] = __bfloat162float(h);
                ll[e] = v[e] - hh[e];
            }
            asm("cvt.rn.bf16x2.f32 %0, %1, %2;" : "=r"(h0) : "f"(hh[1]), "f"(hh[0]));
            asm("cvt.rn.bf16x2.f32 %0, %1, %2;" : "=r"(h1) : "f"(hh[3]), "f"(hh[2]));
            asm("cvt.rn.bf16x2.f32 %0, %1, %2;" : "=r"(l0) : "f"(ll[1]), "f"(ll[0]));
            asm("cvt.rn.bf16x2.f32 %0, %1, %2;" : "=r"(l1) : "f"(ll[3]), "f"(ll[2]));
            g_frag[pass][0][idx] = make_uint2(h0, h1);
            g_frag[pass][1][idx] = make_uint2(l0, l1);
        }
    }
}

// ---------------- K1: conv1 (4->32, k=5, SAME) + bias, stats stage 0 -------
__global__ __launch_bounds__(128) void k_conv1(const float* __restrict__ curve,
                                               const float* __restrict__ w,
                                               const float* __restrict__ bias){
    const int b = blockIdx.x;
    const int t = threadIdx.x;
    extern __shared__ ull smu[];
    ull*   wd  = smu;                     // dup weights: ull[(i*32+c)*8 + k], 1024
    float* cbs = (float*)(wd + 1024);
    float* xin = cbs + 32;                // 4*272
    float* redS= xin + 4*272;
    float* redQ= redS + 32;

    if (t < 32) cbs[t] = bias[t];
    for (int idx = t; idx < 4*272; idx += 128){
        int i = idx / 272, p = idx - i*272, l = p - 2;
        xin[idx] = (l >= 0 && l < LSEQ) ? curve[((size_t)b*4 + i)*LSEQ + l] : 0.f;
    }
    for (int idx = t; idx < 4*32*8; idx += 128){
        int i = idx >> 8, rem = idx & 255, c = rem >> 3, k = rem & 7;
        float v = (k < 5) ? w[c*20 + i*5 + k] : 0.f;
        ((float2*)wd)[idx] = make_float2(v, v);
    }
    __syncthreads();

    const int wrp = t >> 5, lane = t & 31;
    const int c0 = wrp*8, l0 = lane*8;

    ull A[8][4];
#pragma unroll
    for (int cc = 0; cc < 8; cc++){
        float cb = cbs[c0 + cc];
#pragma unroll
        for (int p = 0; p < 4; p++) A[cc][p] = pk(cb, cb);
    }
#pragma unroll
    for (int i = 0; i < 4; i++){
        const float* xb = xin + i*272 + l0;
        float4 u0 = *(const float4*)(xb);
        float4 u1 = *(const float4*)(xb + 4);
        float4 u2 = *(const float4*)(xb + 8);
        float xm[12] = {u0.x,u0.y,u0.z,u0.w, u1.x,u1.y,u1.z,u1.w, u2.x,u2.y,u2.z,u2.w};
        ull P[11];
#pragma unroll
        for (int m = 0; m < 11; m++) P[m] = pk(xm[m], xm[m+1]);
        const ull* wp = wd + (i*32 + c0)*8;
#pragma unroll
        for (int cc = 0; cc < 8; cc++){
            ulonglong2 W01 = *(const ulonglong2*)(wp + cc*8);
            ulonglong2 W23 = *(const ulonglong2*)(wp + cc*8 + 2);
            ull W4 = wp[cc*8 + 4];
#pragma unroll
            for (int p = 0; p < 4; p++){
                ffma2_acc(A[cc][p], P[2*p+0], W01.x);
                ffma2_acc(A[cc][p], P[2*p+1], W01.y);
                ffma2_acc(A[cc][p], P[2*p+2], W23.x);
                ffma2_acc(A[cc][p], P[2*p+3], W23.y);
                ffma2_acc(A[cc][p], P[2*p+4], W4);
            }
        }
    }

    float* outp = g_buf1 + (size_t)b*CH*LSEQ;
#pragma unroll
    for (int cc = 0; cc < 8; cc++){
        float v[8];
#pragma unroll
        for (int p = 0; p < 4; p++) upk(A[cc][p], v[2*p], v[2*p+1]);
        int c = c0 + cc;
        *(float4*)(outp + c*LSEQ + l0)     = make_float4(v[0],v[1],v[2],v[3]);
        *(float4*)(outp + c*LSEQ + l0 + 4) = make_float4(v[4],v[5],v[6],v[7]);
        float s = 0.f, q = 0.f;
#pragma unroll
        for (int m = 0; m < 8; m++){ s += v[m]; q += v[m]*v[m]; }
        s = wred32(s); q = wred32(q);
        if (lane == 0){ redS[c] = s; redQ[c] = q; }
    }
    __syncthreads();
    if (t < 32){
        atomicAdd(&g_stat[0][0][t], (double)redS[t]);
        atomicAdd(&g_stat[0][1][t], (double)redQ[t]);
    }
}

// ---------------- K2/K3: bn+relu -> conv(32->32,k3) via HMMA ---------------
// CTA = half sample (M=128 rows). A K-blocks are row-shifted views of one
// x buffer (shift in ldmatrix base). Shared-operand loop: per k16-step load
// xh,xl (2 ldmatrix) + wh (4 LDS64V) -> 8 MMAs; then wl (4 LDS64V) -> 4 MMAs.
__global__ __launch_bounds__(256, 4) void k_rbmma(int pass,
                                               const float* __restrict__ gam,
                                               const float* __restrict__ bet,
                                               const float* __restrict__ cbias){
    const int b = blockIdx.x >> 1;
    const int lbase = (blockIdx.x & 1) * 128;
    const int t = threadIdx.x;
    const int lane = t & 31, wrp = t >> 5;
    const float* bufIn = (pass == 0) ? g_buf1 : g_buf2;
    float* bufOut = (pass == 0) ? g_buf2 : g_buf3;
    const int stIn = pass, stOut = pass + 1;

    extern __shared__ char smc[];
    const uint32_t smb = smem_u32(smc);
    float* sc  = (float*)(smc + SMSC);
    float* sh  = sc + 32;
    float* cbs = sh + 32;
    float* redS= (float*)(smc + SMRED);
    float* redQ= redS + 256;

    // phase 0: BN constants + copy pre-packed B fragments (1536 uint2)
    if (t < 32){
        const double N = (double)BATCH * (double)LSEQ;
        double S = g_stat[stIn][0][t], Q = g_stat[stIn][1][t];
        double m = S / N, v = Q / N - m*m;
        double s = (double)gam[t] / sqrt(v + EPSBN);
        sc[t] = (float)s;
        sh[t] = (float)((double)bet[t] - m*s);
        cbs[t] = cbias[t];
    }
    {
        const uint4* src = (const uint4*)&g_frag[pass][0][0];
        uint4* dst = (uint4*)(smc + SMWHF);
#pragma unroll
        for (int i = 0; i < 3; i++) dst[t + i*256] = src[t + i*256];
    }
    __syncthreads();

    // phase 1: bn+relu -> x buffer, one write per (row, channel-pair)
    {
        const float* inp = bufIn + (size_t)b*CH*LSEQ;
        for (int idx = t; idx < 16*130; idx += 256){
            int ip = idx / 130, lp = idx - ip*130;
            int i = ip*2;
            int l = lbase + lp - 1;
            float y0 = 0.f, y1 = 0.f;
            if (l >= 0 && l < LSEQ){
                y0 = fmaxf(sc[i]*inp[i*LSEQ + l] + sh[i], 0.f);
                y1 = fmaxf(sc[i+1]*inp[(i+1)*LSEQ + l] + sh[i+1], 0.f);
            }
            uint32_t hp;
            asm("cvt.rn.bf16x2.f32 %0, %1, %2;" : "=r"(hp) : "f"(y1), "f"(y0));
            float h0 = __uint_as_float(hp << 16);
            float h1 = __uint_as_float(hp & 0xffff0000u);
            float e0 = y0 - h0, e1 = y1 - h1;
            uint32_t lp2;
            asm("cvt.rn.bf16x2.f32 %0, %1, %2;" : "=r"(lp2) : "f"(e1), "f"(e0));
            *(uint32_t*)(smc + SMX + lp*STRXB + i*2)      = hp;
            *(uint32_t*)(smc + SMX + lp*STRXB + 64 + i*2) = lp2;
        }
    }
    __syncthreads();

    // mainloop: warp owns rows [m0, m0+16); 6 k16-steps x 12 MMAs
    const int m0 = wrp*16;
    float d[4][4];
#pragma unroll
    for (int tn = 0; tn < 4; tn++)
#pragma unroll
        for (int e = 0; e < 4; e++) d[tn][e] = 0.f;

    const uint32_t axbase = smb + SMX +
        (uint32_t)((m0 + (lane & 15))*STRXB + ((lane & 16) ? 16 : 0));
    const uint32_t bwh = smb + SMWHF + (uint32_t)(lane*8);
    const uint32_t bwl = smb + SMWLF + (uint32_t)(lane*8);

#pragma unroll
    for (int ks6 = 0; ks6 < 6; ks6++){
        const int kk = ks6 >> 1, kc = ks6 & 1;
        const uint32_t aaddr = axbase + (uint32_t)(kk*STRXB + kc*32);
        uint32_t ah0,ah1,ah2,ah3, al0,al1,al2,al3;
        LDMATRIX_X4(ah0,ah1,ah2,ah3, aaddr);          // xh
        LDMATRIX_X4(al0,al1,al2,al3, aaddr + 64);     // xl
        uint32_t b00,b01,b10,b11,b20,b21,b30,b31;
        LDS64V(b00,b01, bwh + (uint32_t)((ks6*4 + 0)*256));
        LDS64V(b10,b11, bwh + (uint32_t)((ks6*4 + 1)*256));
        LDS64V(b20,b21, bwh + (uint32_t)((ks6*4 + 2)*256));
        LDS64V(b30,b31, bwh + (uint32_t)((ks6*4 + 3)*256));
        MMA16816(d[0], ah0,ah1,ah2,ah3, b00,b01);     // xh @ wh
        MMA16816(d[1], ah0,ah1,ah2,ah3, b10,b11);
        MMA16816(d[2], ah0,ah1,ah2,ah3, b20,b21);
        MMA16816(d[3], ah0,ah1,ah2,ah3, b30,b31);
        MMA16816(d[0], al0,al1,al2,al3, b00,b01);     // xl @ wh
        MMA16816(d[1], al0,al1,al2,al3, b10,b11);
        MMA16816(d[2], al0,al1,al2,al3, b20,b21);
        MMA16816(d[3], al0,al1,al2,al3, b30,b31);
        LDS64V(b00,b01, bwl + (uint32_t)((ks6*4 + 0)*256));
        LDS64V(b10,b11, bwl + (uint32_t)((ks6*4 + 1)*256));
        LDS64V(b20,b21, bwl + (uint32_t)((ks6*4 + 2)*256));
        LDS64V(b30,b31, bwl + (uint32_t)((ks6*4 + 3)*256));
        MMA16816(d[0], ah0,ah1,ah2,ah3, b00,b01);     // xh @ wl
        MMA16816(d[1], ah0,ah1,ah2,ah3, b10,b11);
        MMA16816(d[2], ah0,ah1,ah2,ah3, b20,b21);
        MMA16816(d[3], ah0,ah1,ah2,ah3, b30,b31);
    }

    // epilogue: bias, store, per-channel stats
    float* outp = bufOut + (size_t)b*CH*LSEQ + lbase;
    float ps[8], pq[8];
#pragma unroll
    for (int j = 0; j < 8; j++){ ps[j] = 0.f; pq[j] = 0.f; }
    {
        int r0 = m0 + (lane >> 2);
#pragma unroll
        for (int tn = 0; tn < 4; tn++){
            int c0 = tn*8 + (lane & 3)*2;
            float v00 = d[tn][0] + cbs[c0];
            float v01 = d[tn][1] + cbs[c0+1];
            float v10 = d[tn][2] + cbs[c0];
            float v11 = d[tn][3] + cbs[c0+1];
            outp[c0*LSEQ + r0]         = v00;
            outp[(c0+1)*LSEQ + r0]     = v01;
            outp[c0*LSEQ + r0 + 8]     = v10;
            outp[(c0+1)*LSEQ + r0 + 8] = v11;
            ps[tn*2+0] += v00 + v10;  pq[tn*2+0] += v00*v00 + v10*v10;
            ps[tn*2+1] += v01 + v11;  pq[tn*2+1] += v01*v01 + v11*v11;
        }
    }
#pragma unroll
    for (int j = 0; j < 8; j++){
#pragma unroll
        for (int o = 4; o < 32; o <<= 1){
            ps[j] += __shfl_xor_sync(0xffffffffu, ps[j], o);
            pq[j] += __shfl_xor_sync(0xffffffffu, pq[j], o);
        }
    }
    if (lane < 4){
#pragma unroll
        for (int tn = 0; tn < 4; tn++){
#pragma unroll
            for (int p = 0; p < 2; p++){
                int c = tn*8 + lane*2 + p;
                redS[wrp*32 + c] = ps[tn*2+p];
                redQ[wrp*32 + c] = pq[tn*2+p];
            }
        }
    }
    __syncthreads();
    if (t < 32){
        double S = 0.0, Q = 0.0;
#pragma unroll
        for (int wI = 0; wI < 8; wI++){ S += redS[wI*32 + t]; Q += redQ[wI*32 + t]; }
        atomicAdd(&g_stat[stOut][0][t], S);
        atomicAdd(&g_stat[stOut][1][t], Q);
    }
}

// ---------------- K4: bn0+relu, bn2, residual+relu, mean-pool, linear+tanh -
__global__ __launch_bounds__(256) void k_pool_ctx(const float* __restrict__ gamma1,
                                                  const float* __restrict__ beta1,
                                                  const float* __restrict__ gamma3,
                                                  const float* __restrict__ beta3,
                                                  const float* __restrict__ lin_w,
                                                  const float* __restrict__ lin_b){
    const int b = blockIdx.x;
    const int t = threadIdx.x;
    __shared__ float sc0[32], sh0[32], sc2[32], sh2[32];
    __shared__ float red[32][8];
    __shared__ float pooled[32];

    if (t < 32){
        const double N = (double)BATCH * (double)LSEQ;
        { double S = g_stat[0][0][t], Q = g_stat[0][1][t];
          double m = S/N, v = Q/N - m*m;
          double s = (double)gamma1[t] / sqrt(v + EPSBN);
          sc0[t] = (float)s; sh0[t] = (float)((double)beta1[t] - m*s); }
        { double S = g_stat[2][0][t], Q = g_stat[2][1][t];
          double m = S/N, v = Q/N - m*m;
          double s = (double)gamma3[t] / sqrt(v + EPSBN);
          sc2[t] = (float)s; sh2[t] = (float)((double)beta3[t] - m*s); }
    }
    __syncthreads();

    const float* p1 = g_buf1 + (size_t)b*CH*LSEQ;
    const float* p2 = g_buf3 + (size_t)b*CH*LSEQ;
    const int wid = t >> 5, lane = t & 31;
#pragma unroll 1
    for (int c = 0; c < 32; c++){
        float y1 = p1[c*LSEQ + t];
        float h2 = p2[c*LSEQ + t];
        float x1 = fmaxf(sc0[c]*y1 + sh0[c], 0.f);
        float x2 = fmaxf(sc2[c]*h2 + sh2[c] + x1, 0.f);
        float s = wred32(x2);
        if (lane == 0) red[c][wid] = s;
    }
    __syncthreads();
    if (t < 32){
        float s = 0.f;
#pragma unroll
        for (int wI = 0; wI < 8; wI++) s += red[t][wI];
        pooled[t] = s * (1.f/(float)LSEQ);
    }
    __syncthreads();
    if (t < 64){
        float acc = lin_b[t];
#pragma unroll
        for (int c = 0; c < 32; c++) acc += pooled[c]*lin_w[c*64 + t];
        g_ctx[(size_t)b*64 + t] = tanhf(acc);
    }
}

// ---------------- K5: 10 coupling layers, 64 rows per block, all in smem ---
__global__ __launch_bounds__(256) void k_coupling(const float* __restrict__ zin,
                                                  const float* __restrict__ W1,
                                                  const float* __restrict__ B1w,
                                                  const float* __restrict__ W2,
                                                  const float* __restrict__ B2w,
                                                  const float* __restrict__ W3,
                                                  const float* __restrict__ B3w,
                                                  float* __restrict__ outp){
    const int t = threadIdx.x;
    const int rowBase = blockIdx.x * 64;
    extern __shared__ float sm[];
    float* nin = sm;
    float* hA  = nin + 64*76;
    float* hB  = hA  + 64*132;
    float* zz  = hB  + 64*132;
    float* ob  = zz  + 64*12;
    float* ldv = ob  + 64*20;

    for (int idx = t; idx < 64*9; idx += 256){
        int r = idx/9, j = idx - r*9;
        zz[r*12 + j] = zin[(size_t)(rowBase + r)*9 + j];
    }
    for (int idx = t; idx < 64*64; idx += 256){
        int r = idx >> 6, j = idx & 63;
        nin[r*76 + 9 + j] = g_ctx[(size_t)(rowBase + r)*64 + j];
    }
    if (t < 64) ldv[t] = 0.f;
    __syncthreads();

    const int jc = t & 31;
    const int r0 = (t >> 5) * 8;

    for (int layer = 0; layer < 10; ++layer){
        if (t < 64){
#pragma unroll
            for (int j = 0; j < 9; j++){
                float m = (((j + layer) & 1) == 0) ? 1.f : 0.f;
                nin[t*76 + j] = zz[t*12 + j] * m;
            }
        }
        __syncthreads();
        {
            const float* Wl = W1 + (size_t)layer*73*128;
            float4 bb = *(const float4*)(B1w + layer*128 + 4*jc);
            ull acc[8][2];
#pragma unroll
            for (int r = 0; r < 8; r++){ acc[r][0] = pk(bb.x, bb.y); acc[r][1] = pk(bb.z, bb.w); }
#pragma unroll 2
            for (int i = 0; i < 73; i++){
                ulonglong2 wv = *(const ulonglong2*)(Wl + i*128 + 4*jc);
#pragma unroll
                for (int r = 0; r < 8; r++){
                    float x = nin[(r0 + r)*76 + i];
                    ull xx = pk(x, x);
                    ffma2_acc(acc[r][0], xx, wv.x);
                    ffma2_acc(acc[r][1], xx, wv.y);
                }
            }
#pragma unroll
            for (int r = 0; r < 8; r++){
                float v0,v1,v2,v3;
                upk(acc[r][0], v0, v1); upk(acc[r][1], v2, v3);
                *(float4*)(hA + (r0 + r)*132 + 4*jc) =
                    make_float4(fmaxf(v0,0.f), fmaxf(v1,0.f), fmaxf(v2,0.f), fmaxf(v3,0.f));
            }
        }
        __syncthreads();
        {
            const float* Wl = W2 + (size_t)layer*128*128;
            float4 bb = *(const float4*)(B2w + layer*128 + 4*jc);
            ull acc[8][2];
#pragma unroll
            for (int r = 0; r < 8; r++){ acc[r][0] = pk(bb.x, bb.y); acc[r][1] = pk(bb.z, bb.w); }
#pragma unroll 2
            for (int i = 0; i < 128; i++){
                ulonglong2 wv = *(const ulonglong2*)(Wl + i*128 + 4*jc);
#pragma unroll
                for (int r = 0; r < 8; r++){
                    float x = hA[(r0 + r)*132 + i];
                    ull xx = pk(x, x);
                    ffma2_acc(acc[r][0], xx, wv.x);
                    ffma2_acc(acc[r][1], xx, wv.y);
                }
            }
#pragma unroll
            for (int r = 0; r < 8; r++){
                float v0,v1,v2,v3;
                upk(acc[r][0], v0, v1); upk(acc[r][1], v2, v3);
                *(float4*)(hB + (r0 + r)*132 + 4*jc) =
                    make_float4(fmaxf(v0,0.f), fmaxf(v1,0.f), fmaxf(v2,0.f), fmaxf(v3,0.f));
            }
        }
        __syncthreads();
        {
            const float* Wl = W3 + (size_t)layer*128*18;
            const int r = t >> 2, q = t & 3;
            float acc[5] = {0.f,0.f,0.f,0.f,0.f};
#pragma unroll 2
            for (int i = 0; i < 128; i++){
                float x = hB[r*132 + i];
#pragma unroll
                for (int k = 0; k < 5; k++){
                    int j = q + 4*k;
                    if (j < 18) acc[k] = fmaf(x, __ldg(Wl + i*18 + j), acc[k]);
                }
            }
#pragma unroll
            for (int k = 0; k < 5; k++){
                int j = q + 4*k;
                if (j < 18) ob[r*20 + j] = acc[k] + B3w[layer*18 + j];
            }
        }
        __syncthreads();
        if (t < 64){
            float ldl = ldv[t];
#pragma unroll
            for (int j = 0; j < 9; j++){
                if (((j + layer) & 1) != 0){
                    float s  = tanhf(ob[t*20 + j]);
                    float tt = ob[t*20 + 9 + j];
                    zz[t*12 + j] = zz[t*12 + j]*expf(s) + tt;
                    ldl += s;
                }
            }
            ldv[t] = ldl;
        }
        __syncthreads();
    }

    if (t < 64){
        float lp = 0.f;
#pragma unroll
        for (int j = 0; j < 9; j++){
            float z = zz[t*12 + j];
            lp += LOG2PI + z*z;
        }
        outp[rowBase + t] = ldv[t] - 0.5f*lp;
    }
}

// ---------------- launch ----------------------------------------------------
extern "C" void kernel_launch(void* const* d_in, const int* in_sizes, int n_in,
                              void* d_out, int out_size){
    const float* inputs  = (const float*)d_in[0];
    const float* curve   = (const float*)d_in[1];
    const float* conv1_w = (const float*)d_in[2];
    const float* conv1_b = (const float*)d_in[3];
    const float* bn1_g   = (const float*)d_in[4];
    const float* bn1_b   = (const float*)d_in[5];
    const float* rb_w1   = (const float*)d_in[6];
    const float* rb_b1   = (const float*)d_in[7];
    const float* rb_g1   = (const float*)d_in[8];
    const float* rb_be1  = (const float*)d_in[9];
    const float* rb_w2   = (const float*)d_in[10];
    const float* rb_b2   = (const float*)d_in[11];
    const float* rb_g2   = (const float*)d_in[12];
    const float* rb_be2  = (const float*)d_in[13];
    const float* lin_w   = (const float*)d_in[14];
    const float* lin_b   = (const float*)d_in[15];
    const float* W1      = (const float*)d_in[16];
    const float* B1      = (const float*)d_in[17];
    const float* W2      = (const float*)d_in[18];
    const float* B2      = (const float*)d_in[19];
    const float* W3      = (const float*)d_in[20];
    const float* B3      = (const float*)d_in[21];
    float* out = (float*)d_out;

    const int smem1 = 1024*8 + (32 + 4*272 + 32 + 32) * 4;
    const int smemC = (64*76 + 64*132*2 + 64*12 + 64*20 + 64) * 4;

    cudaFuncSetAttribute(k_conv1,    cudaFuncAttributeMaxDynamicSharedMemorySize, smem1);
    cudaFuncSetAttribute(k_rbmma,    cudaFuncAttributeMaxDynamicSharedMemorySize, SM_TOTAL_M);
    cudaFuncSetAttribute(k_coupling, cudaFuncAttributeMaxDynamicSharedMemorySize, smemC);

    k_prep<<<1, 256>>>(rb_w1, rb_w2);
    k_conv1<<<BATCH, 128, smem1>>>(curve, conv1_w, conv1_b);
    k_rbmma<<<BATCH*2, 256, SM_TOTAL_M>>>(0, bn1_g, bn1_b, rb_b1);
    k_rbmma<<<BATCH*2, 256, SM_TOTAL_M>>>(1, rb_g1, rb_be1, rb_b2);
    k_pool_ctx<<<BATCH, 256>>>(bn1_g, bn1_b, rb_g2, rb_be2, lin_w, lin_b);
    k_coupling<<<BATCH/64, 256, smemC>>>(inputs, W1, B1, W2, B2, W3, B3, out);
}

// round 12
// speedup vs baseline: 1.7685x; 1.0016x over previous
#include <cuda_runtime.h>
#include <cuda_bf16.h>
#include <cstdint>

#define BATCH 16384
#define LSEQ  256
#define CH    32
#define EPSBN 1e-5
#define LOG2PI 1.8378770664093453f

typedef unsigned long long ull;

// ---------------- scratch (device-global; no runtime alloc allowed) -------
__device__ float  g_buf1[(size_t)BATCH*CH*LSEQ];   // conv1 output (pre-BN)
__device__ float  g_buf2[(size_t)BATCH*CH*LSEQ];   // h1 (pre-BN)
__device__ float  g_buf3[(size_t)BATCH*CH*LSEQ];   // h2 (pre-BN)
__device__ float  g_ctx [(size_t)BATCH*64];        // context vectors
__device__ double g_stat[3][2][32];                // [stage][sum|sumsq][channel]
__device__ uint2  g_frag[2][2][768];               // [pass][wh|wl][(ks6*4+tn)*32+lane]

// ---------------- packed fp32x2 helpers (FFMA2, conv1/coupling) ------------
__device__ __forceinline__ ull pk(float lo, float hi){
    ull r; asm("mov.b64 %0, {%1,%2};" : "=l"(r) : "f"(lo), "f"(hi)); return r;
}
__device__ __forceinline__ void upk(ull v, float& lo, float& hi){
    asm("mov.b64 {%0,%1}, %2;" : "=f"(lo), "=f"(hi) : "l"(v));
}
__device__ __forceinline__ void ffma2_acc(ull& a, ull b, ull c){
    asm("fma.rn.f32x2 %0, %1, %2, %0;" : "+l"(a) : "l"(b), "l"(c));
}
__device__ __forceinline__ float wred32(float v){
#pragma unroll
    for (int o = 16; o > 0; o >>= 1) v += __shfl_xor_sync(0xffffffffu, v, o);
    return v;
}
__device__ __forceinline__ uint32_t smem_u32(const void* p){
    uint32_t a;
    asm("{ .reg .u64 t; cvta.to.shared.u64 t, %1; cvt.u32.u64 %0, t; }" : "=r"(a) : "l"(p));
    return a;
}

// ---------------- warp-MMA helpers (baseline PTX, works on sm_103) --------
#define LDMATRIX_X4(a0,a1,a2,a3, addr) \
    asm volatile("ldmatrix.sync.aligned.m8n8.x4.shared.b16 {%0,%1,%2,%3}, [%4];" \
        : "=r"(a0), "=r"(a1), "=r"(a2), "=r"(a3) : "r"(addr))
#define LDS64V(x0,x1, addr) \
    asm volatile("ld.shared.v2.u32 {%0,%1}, [%2];" : "=r"(x0), "=r"(x1) : "r"(addr))
#define MMA16816(d, a0,a1,a2,a3, b0,b1) \
    asm volatile("mma.sync.aligned.m16n8k16.row.col.f32.bf16.bf16.f32 " \
        "{%0,%1,%2,%3}, {%4,%5,%6,%7}, {%8,%9}, {%0,%1,%2,%3};" \
        : "+f"((d)[0]), "+f"((d)[1]), "+f"((d)[2]), "+f"((d)[3]) \
        : "r"(a0), "r"(a1), "r"(a2), "r"(a3), "r"(b0), "r"(b1))

// x buffer: 131 rows x 144 bytes (32 xh bf16 | 32 xl bf16, 16B pad)
#define STRXB 144
// smem byte offsets for k_rbmma
#define SMX    0            // 131*144 = 18864
#define SMWHF  18864        // 768 uint2 = 6144
#define SMWLF  25008        // 6144
#define SMSC   31152        // sc[32], sh[32], cbs[32] = 384
#define SMRED  31536        // redS[8][32], redQ[8][32] = 2048
#define SM_TOTAL_M 33584

// ---------------- K0: zero stats + pre-pack B fragments --------------------
__global__ void k_prep(const float* __restrict__ w1, const float* __restrict__ w2){
    const int t = threadIdx.x;
    if (t < 192) (&g_stat[0][0][0])[t] = 0.0;
#pragma unroll 1
    for (int pass = 0; pass < 2; pass++){
        const float* w = pass ? w2 : w1;
        for (int idx = t; idx < 768; idx += 256){
            int ks6 = idx >> 7, rem = idx & 127, tn = rem >> 5, lane = rem & 31;
            int n = tn*8 + (lane >> 2);
            int kb = ks6*16 + (lane & 3)*2;
            float v[4];
#pragma unroll
            for (int e = 0; e < 4; e++){
                int k = kb + (e >> 1)*8 + (e & 1);      // kb, kb+1, kb+8, kb+9
                int i = k & 31, kkb = k >> 5;
                v[e] = w[n*96 + i*3 + kkb];
            }
            uint32_t h0, h1, l0, l1;
            float hh[4], ll[4];
#pragma unroll
            for (int e = 0; e < 4; e++){
                __nv_bfloat16 h = __float2bfloat16(v[e]);
                hh[e] = __bfloat162float(h);
                ll[e] = v[e] - hh[e];
            }
            asm("cvt.rn.bf16x2.f32 %0, %1, %2;" : "=r"(h0) : "f"(hh[1]), "f"(hh[0]));
            asm("cvt.rn.bf16x2.f32 %0, %1, %2;" : "=r"(h1) : "f"(hh[3]), "f"(hh[2]));
            asm("cvt.rn.bf16x2.f32 %0, %1, %2;" : "=r"(l0) : "f"(ll[1]), "f"(ll[0]));
            asm("cvt.rn.bf16x2.f32 %0, %1, %2;" : "=r"(l1) : "f"(ll[3]), "f"(ll[2]));
            g_frag[pass][0][idx] = make_uint2(h0, h1);
            g_frag[pass][1][idx] = make_uint2(l0, l1);
        }
    }
}

// ---------------- K1: conv1 (4->32, k=5, SAME) + bias, stats stage 0 -------
__global__ __launch_bounds__(128) void k_conv1(const float* __restrict__ curve,
                                               const float* __restrict__ w,
                                               const float* __restrict__ bias){
    const int b = blockIdx.x;
    const int t = threadIdx.x;
    extern __shared__ ull smu[];
    ull*   wd  = smu;                     // dup weights: ull[(i*32+c)*8 + k], 1024
    float* cbs = (float*)(wd + 1024);
    float* xin = cbs + 32;                // 4*272
    float* redS= xin + 4*272;
    float* redQ= redS + 32;

    if (t < 32) cbs[t] = bias[t];
    for (int idx = t; idx < 4*272; idx += 128){
        int i = idx / 272, p = idx - i*272, l = p - 2;
        xin[idx] = (l >= 0 && l < LSEQ) ? curve[((size_t)b*4 + i)*LSEQ + l] : 0.f;
    }
    for (int idx = t; idx < 4*32*8; idx += 128){
        int i = idx >> 8, rem = idx & 255, c = rem >> 3, k = rem & 7;
        float v = (k < 5) ? w[c*20 + i*5 + k] : 0.f;
        ((float2*)wd)[idx] = make_float2(v, v);
    }
    __syncthreads();

    const int wrp = t >> 5, lane = t & 31;
    const int c0 = wrp*8, l0 = lane*8;

    ull A[8][4];
#pragma unroll
    for (int cc = 0; cc < 8; cc++){
        float cb = cbs[c0 + cc];
#pragma unroll
        for (int p = 0; p < 4; p++) A[cc][p] = pk(cb, cb);
    }
#pragma unroll
    for (int i = 0; i < 4; i++){
        const float* xb = xin + i*272 + l0;
        float4 u0 = *(const float4*)(xb);
        float4 u1 = *(const float4*)(xb + 4);
        float4 u2 = *(const float4*)(xb + 8);
        float xm[12] = {u0.x,u0.y,u0.z,u0.w, u1.x,u1.y,u1.z,u1.w, u2.x,u2.y,u2.z,u2.w};
        ull P[11];
#pragma unroll
        for (int m = 0; m < 11; m++) P[m] = pk(xm[m], xm[m+1]);
        const ull* wp = wd + (i*32 + c0)*8;
#pragma unroll
        for (int cc = 0; cc < 8; cc++){
            ulonglong2 W01 = *(const ulonglong2*)(wp + cc*8);
            ulonglong2 W23 = *(const ulonglong2*)(wp + cc*8 + 2);
            ull W4 = wp[cc*8 + 4];
#pragma unroll
            for (int p = 0; p < 4; p++){
                ffma2_acc(A[cc][p], P[2*p+0], W01.x);
                ffma2_acc(A[cc][p], P[2*p+1], W01.y);
                ffma2_acc(A[cc][p], P[2*p+2], W23.x);
                ffma2_acc(A[cc][p], P[2*p+3], W23.y);
                ffma2_acc(A[cc][p], P[2*p+4], W4);
            }
        }
    }

    float* outp = g_buf1 + (size_t)b*CH*LSEQ;
#pragma unroll
    for (int cc = 0; cc < 8; cc++){
        float v[8];
#pragma unroll
        for (int p = 0; p < 4; p++) upk(A[cc][p], v[2*p], v[2*p+1]);
        int c = c0 + cc;
        *(float4*)(outp + c*LSEQ + l0)     = make_float4(v[0],v[1],v[2],v[3]);
        *(float4*)(outp + c*LSEQ + l0 + 4) = make_float4(v[4],v[5],v[6],v[7]);
        float s = 0.f, q = 0.f;
#pragma unroll
        for (int m = 0; m < 8; m++){ s += v[m]; q += v[m]*v[m]; }
        s = wred32(s); q = wred32(q);
        if (lane == 0){ redS[c] = s; redQ[c] = q; }
    }
    __syncthreads();
    if (t < 32){
        atomicAdd(&g_stat[0][0][t], (double)redS[t]);
        atomicAdd(&g_stat[0][1][t], (double)redQ[t]);
    }
}

// ---------------- K2/K3: bn+relu -> conv(32->32,k3) via HMMA ---------------
// CTA = half sample (M=128 rows). A K-blocks are row-shifted views of one
// x buffer. Double-buffered mainloop: prefetch A(k+1)+wh(k+1) during MMAs(k).
__global__ __launch_bounds__(256, 3) void k_rbmma(int pass,
                                               const float* __restrict__ gam,
                                               const float* __restrict__ bet,
                                               const float* __restrict__ cbias){
    const int b = blockIdx.x >> 1;
    const int lbase = (blockIdx.x & 1) * 128;
    const int t = threadIdx.x;
    const int lane = t & 31, wrp = t >> 5;
    const float* bufIn = (pass == 0) ? g_buf1 : g_buf2;
    float* bufOut = (pass == 0) ? g_buf2 : g_buf3;
    const int stIn = pass, stOut = pass + 1;

    extern __shared__ char smc[];
    const uint32_t smb = smem_u32(smc);
    float* sc  = (float*)(smc + SMSC);
    float* sh  = sc + 32;
    float* cbs = sh + 32;
    float* redS= (float*)(smc + SMRED);
    float* redQ= redS + 256;

    // phase 0: BN constants + copy pre-packed B fragments (1536 uint2)
    if (t < 32){
        const double N = (double)BATCH * (double)LSEQ;
        double S = g_stat[stIn][0][t], Q = g_stat[stIn][1][t];
        double m = S / N, v = Q / N - m*m;
        double s = (double)gam[t] / sqrt(v + EPSBN);
        sc[t] = (float)s;
        sh[t] = (float)((double)bet[t] - m*s);
        cbs[t] = cbias[t];
    }
    {
        const uint4* src = (const uint4*)&g_frag[pass][0][0];
        uint4* dst = (uint4*)(smc + SMWHF);
#pragma unroll
        for (int i = 0; i < 3; i++) dst[t + i*256] = src[t + i*256];
    }
    __syncthreads();

    // phase 1: bn+relu -> x buffer, one write per (row, channel-pair)
    {
        const float* inp = bufIn + (size_t)b*CH*LSEQ;
        for (int idx = t; idx < 16*130; idx += 256){
            int ip = idx / 130, lp = idx - ip*130;
            int i = ip*2;
            int l = lbase + lp - 1;
            float y0 = 0.f, y1 = 0.f;
            if (l >= 0 && l < LSEQ){
                y0 = fmaxf(sc[i]*inp[i*LSEQ + l] + sh[i], 0.f);
                y1 = fmaxf(sc[i+1]*inp[(i+1)*LSEQ + l] + sh[i+1], 0.f);
            }
            uint32_t hp;
            asm("cvt.rn.bf16x2.f32 %0, %1, %2;" : "=r"(hp) : "f"(y1), "f"(y0));
            float h0 = __uint_as_float(hp << 16);
            float h1 = __uint_as_float(hp & 0xffff0000u);
            float e0 = y0 - h0, e1 = y1 - h1;
            uint32_t lp2;
            asm("cvt.rn.bf16x2.f32 %0, %1, %2;" : "=r"(lp2) : "f"(e1), "f"(e0));
            *(uint32_t*)(smc + SMX + lp*STRXB + i*2)      = hp;
            *(uint32_t*)(smc + SMX + lp*STRXB + 64 + i*2) = lp2;
        }
    }
    __syncthreads();

    // mainloop: warp owns rows [m0, m0+16); double-buffered over 6 k16-steps
    const int m0 = wrp*16;
    float d[4][4];
#pragma unroll
    for (int tn = 0; tn < 4; tn++)
#pragma unroll
        for (int e = 0; e < 4; e++) d[tn][e] = 0.f;

    const uint32_t axbase = smb + SMX +
        (uint32_t)((m0 + (lane & 15))*STRXB + ((lane & 16) ? 16 : 0));
    const uint32_t bwh = smb + SMWHF + (uint32_t)(lane*8);
    const uint32_t bwl = smb + SMWLF + (uint32_t)(lane*8);

    uint32_t ah[2][4], al[2][4], bh[2][8];
    // prologue: load step 0
    {
        LDMATRIX_X4(ah[0][0],ah[0][1],ah[0][2],ah[0][3], axbase);
        LDMATRIX_X4(al[0][0],al[0][1],al[0][2],al[0][3], axbase + 64);
        LDS64V(bh[0][0],bh[0][1], bwh + 0*256);
        LDS64V(bh[0][2],bh[0][3], bwh + 1*256);
        LDS64V(bh[0][4],bh[0][5], bwh + 2*256);
        LDS64V(bh[0][6],bh[0][7], bwh + 3*256);
    }

#pragma unroll
    for (int ks6 = 0; ks6 < 6; ks6++){
        const int cur = ks6 & 1, nxt = cur ^ 1;
        if (ks6 < 5){
            const int kn = ks6 + 1;
            const uint32_t anext = axbase + (uint32_t)((kn >> 1)*STRXB + (kn & 1)*32);
            LDMATRIX_X4(ah[nxt][0],ah[nxt][1],ah[nxt][2],ah[nxt][3], anext);
            LDMATRIX_X4(al[nxt][0],al[nxt][1],al[nxt][2],al[nxt][3], anext + 64);
            LDS64V(bh[nxt][0],bh[nxt][1], bwh + (uint32_t)((kn*4 + 0)*256));
            LDS64V(bh[nxt][2],bh[nxt][3], bwh + (uint32_t)((kn*4 + 1)*256));
            LDS64V(bh[nxt][4],bh[nxt][5], bwh + (uint32_t)((kn*4 + 2)*256));
            LDS64V(bh[nxt][6],bh[nxt][7], bwh + (uint32_t)((kn*4 + 3)*256));
        }
        MMA16816(d[0], ah[cur][0],ah[cur][1],ah[cur][2],ah[cur][3], bh[cur][0],bh[cur][1]);  // xh@wh
        MMA16816(d[1], ah[cur][0],ah[cur][1],ah[cur][2],ah[cur][3], bh[cur][2],bh[cur][3]);
        MMA16816(d[2], ah[cur][0],ah[cur][1],ah[cur][2],ah[cur][3], bh[cur][4],bh[cur][5]);
        MMA16816(d[3], ah[cur][0],ah[cur][1],ah[cur][2],ah[cur][3], bh[cur][6],bh[cur][7]);
        MMA16816(d[0], al[cur][0],al[cur][1],al[cur][2],al[cur][3], bh[cur][0],bh[cur][1]);  // xl@wh
        MMA16816(d[1], al[cur][0],al[cur][1],al[cur][2],al[cur][3], bh[cur][2],bh[cur][3]);
        MMA16816(d[2], al[cur][0],al[cur][1],al[cur][2],al[cur][3], bh[cur][4],bh[cur][5]);
        MMA16816(d[3], al[cur][0],al[cur][1],al[cur][2],al[cur][3], bh[cur][6],bh[cur][7]);
        uint32_t bl[8];
        LDS64V(bl[0],bl[1], bwl + (uint32_t)((ks6*4 + 0)*256));
        LDS64V(bl[2],bl[3], bwl + (uint32_t)((ks6*4 + 1)*256));
        LDS64V(bl[4],bl[5], bwl + (uint32_t)((ks6*4 + 2)*256));
        LDS64V(bl[6],bl[7], bwl + (uint32_t)((ks6*4 + 3)*256));
        MMA16816(d[0], ah[cur][0],ah[cur][1],ah[cur][2],ah[cur][3], bl[0],bl[1]);            // xh@wl
        MMA16816(d[1], ah[cur][0],ah[cur][1],ah[cur][2],ah[cur][3], bl[2],bl[3]);
        MMA16816(d[2], ah[cur][0],ah[cur][1],ah[cur][2],ah[cur][3], bl[4],bl[5]);
        MMA16816(d[3], ah[cur][0],ah[cur][1],ah[cur][2],ah[cur][3], bl[6],bl[7]);
    }

    // epilogue: bias, store, per-channel stats
    float* outp = bufOut + (size_t)b*CH*LSEQ + lbase;
    float ps[8], pq[8];
#pragma unroll
    for (int j = 0; j < 8; j++){ ps[j] = 0.f; pq[j] = 0.f; }
    {
        int r0 = m0 + (lane >> 2);
#pragma unroll
        for (int tn = 0; tn < 4; tn++){
            int c0 = tn*8 + (lane & 3)*2;
            float v00 = d[tn][0] + cbs[c0];
            float v01 = d[tn][1] + cbs[c0+1];
            float v10 = d[tn][2] + cbs[c0];
            float v11 = d[tn][3] + cbs[c0+1];
            outp[c0*LSEQ + r0]         = v00;
            outp[(c0+1)*LSEQ + r0]     = v01;
            outp[c0*LSEQ + r0 + 8]     = v10;
            outp[(c0+1)*LSEQ + r0 + 8] = v11;
            ps[tn*2+0] += v00 + v10;  pq[tn*2+0] += v00*v00 + v10*v10;
            ps[tn*2+1] += v01 + v11;  pq[tn*2+1] += v01*v01 + v11*v11;
        }
    }
#pragma unroll
    for (int j = 0; j < 8; j++){
#pragma unroll
        for (int o = 4; o < 32; o <<= 1){
            ps[j] += __shfl_xor_sync(0xffffffffu, ps[j], o);
            pq[j] += __shfl_xor_sync(0xffffffffu, pq[j], o);
        }
    }
    if (lane < 4){
#pragma unroll
        for (int tn = 0; tn < 4; tn++){
#pragma unroll
            for (int p = 0; p < 2; p++){
                int c = tn*8 + lane*2 + p;
                redS[wrp*32 + c] = ps[tn*2+p];
                redQ[wrp*32 + c] = pq[tn*2+p];
            }
        }
    }
    __syncthreads();
    if (t < 32){
        double S = 0.0, Q = 0.0;
#pragma unroll
        for (int wI = 0; wI < 8; wI++){ S += redS[wI*32 + t]; Q += redQ[wI*32 + t]; }
        atomicAdd(&g_stat[stOut][0][t], S);
        atomicAdd(&g_stat[stOut][1][t], Q);
    }
}

// ---------------- K4: bn0+relu, bn2, residual+relu, mean-pool, linear+tanh -
__global__ __launch_bounds__(256) void k_pool_ctx(const float* __restrict__ gamma1,
                                                  const float* __restrict__ beta1,
                                                  const float* __restrict__ gamma3,
                                                  const float* __restrict__ beta3,
                                                  const float* __restrict__ lin_w,
                                                  const float* __restrict__ lin_b){
    const int b = blockIdx.x;
    const int t = threadIdx.x;
    __shared__ float sc0[32], sh0[32], sc2[32], sh2[32];
    __shared__ float red[32][8];
    __shared__ float pooled[32];

    if (t < 32){
        const double N = (double)BATCH * (double)LSEQ;
        { double S = g_stat[0][0][t], Q = g_stat[0][1][t];
          double m = S/N, v = Q/N - m*m;
          double s = (double)gamma1[t] / sqrt(v + EPSBN);
          sc0[t] = (float)s; sh0[t] = (float)((double)beta1[t] - m*s); }
        { double S = g_stat[2][0][t], Q = g_stat[2][1][t];
          double m = S/N, v = Q/N - m*m;
          double s = (double)gamma3[t] / sqrt(v + EPSBN);
          sc2[t] = (float)s; sh2[t] = (float)((double)beta3[t] - m*s); }
    }
    __syncthreads();

    const float* p1 = g_buf1 + (size_t)b*CH*LSEQ;
    const float* p2 = g_buf3 + (size_t)b*CH*LSEQ;
    const int wid = t >> 5, lane = t & 31;
#pragma unroll 1
    for (int c = 0; c < 32; c++){
        float y1 = p1[c*LSEQ + t];
        float h2 = p2[c*LSEQ + t];
        float x1 = fmaxf(sc0[c]*y1 + sh0[c], 0.f);
        float x2 = fmaxf(sc2[c]*h2 + sh2[c] + x1, 0.f);
        float s = wred32(x2);
        if (lane == 0) red[c][wid] = s;
    }
    __syncthreads();
    if (t < 32){
        float s = 0.f;
#pragma unroll
        for (int wI = 0; wI < 8; wI++) s += red[t][wI];
        pooled[t] = s * (1.f/(float)LSEQ);
    }
    __syncthreads();
    if (t < 64){
        float acc = lin_b[t];
#pragma unroll
        for (int c = 0; c < 32; c++) acc += pooled[c]*lin_w[c*64 + t];
        g_ctx[(size_t)b*64 + t] = tanhf(acc);
    }
}

// ---------------- K5: 10 coupling layers, 64 rows per block, all in smem ---
__global__ __launch_bounds__(256) void k_coupling(const float* __restrict__ zin,
                                                  const float* __restrict__ W1,
                                                  const float* __restrict__ B1w,
                                                  const float* __restrict__ W2,
                                                  const float* __restrict__ B2w,
                                                  const float* __restrict__ W3,
                                                  const float* __restrict__ B3w,
                                                  float* __restrict__ outp){
    const int t = threadIdx.x;
    const int rowBase = blockIdx.x * 64;
    extern __shared__ float sm[];
    float* nin = sm;
    float* hA  = nin + 64*76;
    float* hB  = hA  + 64*132;
    float* zz  = hB  + 64*132;
    float* ob  = zz  + 64*12;
    float* ldv = ob  + 64*20;

    for (int idx = t; idx < 64*9; idx += 256){
        int r = idx/9, j = idx - r*9;
        zz[r*12 + j] = zin[(size_t)(rowBase + r)*9 + j];
    }
    for (int idx = t; idx < 64*64; idx += 256){
        int r = idx >> 6, j = idx & 63;
        nin[r*76 + 9 + j] = g_ctx[(size_t)(rowBase + r)*64 + j];
    }
    if (t < 64) ldv[t] = 0.f;
    __syncthreads();

    const int jc = t & 31;
    const int r0 = (t >> 5) * 8;

    for (int layer = 0; layer < 10; ++layer){
        if (t < 64){
#pragma unroll
            for (int j = 0; j < 9; j++){
                float m = (((j + layer) & 1) == 0) ? 1.f : 0.f;
                nin[t*76 + j] = zz[t*12 + j] * m;
            }
        }
        __syncthreads();
        {
            const float* Wl = W1 + (size_t)layer*73*128;
            float4 bb = *(const float4*)(B1w + layer*128 + 4*jc);
            ull acc[8][2];
#pragma unroll
            for (int r = 0; r < 8; r++){ acc[r][0] = pk(bb.x, bb.y); acc[r][1] = pk(bb.z, bb.w); }
#pragma unroll 2
            for (int i = 0; i < 73; i++){
                ulonglong2 wv = *(const ulonglong2*)(Wl + i*128 + 4*jc);
#pragma unroll
                for (int r = 0; r < 8; r++){
                    float x = nin[(r0 + r)*76 + i];
                    ull xx = pk(x, x);
                    ffma2_acc(acc[r][0], xx, wv.x);
                    ffma2_acc(acc[r][1], xx, wv.y);
                }
            }
#pragma unroll
            for (int r = 0; r < 8; r++){
                float v0,v1,v2,v3;
                upk(acc[r][0], v0, v1); upk(acc[r][1], v2, v3);
                *(float4*)(hA + (r0 + r)*132 + 4*jc) =
                    make_float4(fmaxf(v0,0.f), fmaxf(v1,0.f), fmaxf(v2,0.f), fmaxf(v3,0.f));
            }
        }
        __syncthreads();
        {
            const float* Wl = W2 + (size_t)layer*128*128;
            float4 bb = *(const float4*)(B2w + layer*128 + 4*jc);
            ull acc[8][2];
#pragma unroll
            for (int r = 0; r < 8; r++){ acc[r][0] = pk(bb.x, bb.y); acc[r][1] = pk(bb.z, bb.w); }
#pragma unroll 2
            for (int i = 0; i < 128; i++){
                ulonglong2 wv = *(const ulonglong2*)(Wl + i*128 + 4*jc);
#pragma unroll
                for (int r = 0; r < 8; r++){
                    float x = hA[(r0 + r)*132 + i];
                    ull xx = pk(x, x);
                    ffma2_acc(acc[r][0], xx, wv.x);
                    ffma2_acc(acc[r][1], xx, wv.y);
                }
            }
#pragma unroll
            for (int r = 0; r < 8; r++){
                float v0,v1,v2,v3;
                upk(acc[r][0], v0, v1); upk(acc[r][1], v2, v3);
                *(float4*)(hB + (r0 + r)*132 + 4*jc) =
                    make_float4(fmaxf(v0,0.f), fmaxf(v1,0.f), fmaxf(v2,0.f), fmaxf(v3,0.f));
            }
        }
        __syncthreads();
        {
            const float* Wl = W3 + (size_t)layer*128*18;
            const int r = t >> 2, q = t & 3;
            float acc[5] = {0.f,0.f,0.f,0.f,0.f};
#pragma unroll 2
            for (int i = 0; i < 128; i++){
                float x = hB[r*132 + i];
#pragma unroll
                for (int k = 0; k < 5; k++){
                    int j = q + 4*k;
                    if (j < 18) acc[k] = fmaf(x, __ldg(Wl + i*18 + j), acc[k]);
                }
            }
#pragma unroll
            for (int k = 0; k < 5; k++){
                int j = q + 4*k;
                if (j < 18) ob[r*20 + j] = acc[k] + B3w[layer*18 + j];
            }
        }
        __syncthreads();
        if (t < 64){
            float ldl = ldv[t];
#pragma unroll
            for (int j = 0; j < 9; j++){
                if (((j + layer) & 1) != 0){
                    float s  = tanhf(ob[t*20 + j]);
                    float tt = ob[t*20 + 9 + j];
                    zz[t*12 + j] = zz[t*12 + j]*expf(s) + tt;
                    ldl += s;
                }
            }
            ldv[t] = ldl;
        }
        __syncthreads();
    }

    if (t < 64){
        float lp = 0.f;
#pragma unroll
        for (int j = 0; j < 9; j++){
            float z = zz[t*12 + j];
            lp += LOG2PI + z*z;
        }
        outp[rowBase + t] = ldv[t] - 0.5f*lp;
    }
}

// ---------------- launch ----------------------------------------------------
extern "C" void kernel_launch(void* const* d_in, const int* in_sizes, int n_in,
                              void* d_out, int out_size){
    const float* inputs  = (const float*)d_in[0];
    const float* curve   = (const float*)d_in[1];
    const float* conv1_w = (const float*)d_in[2];
    const float* conv1_b = (const float*)d_in[3];
    const float* bn1_g   = (const float*)d_in[4];
    const float* bn1_b   = (const float*)d_in[5];
    const float* rb_w1   = (const float*)d_in[6];
    const float* rb_b1   = (const float*)d_in[7];
    const float* rb_g1   = (const float*)d_in[8];
    const float* rb_be1  = (const float*)d_in[9];
    const float* rb_w2   = (const float*)d_in[10];
    const float* rb_b2   = (const float*)d_in[11];
    const float* rb_g2   = (const float*)d_in[12];
    const float* rb_be2  = (const float*)d_in[13];
    const float* lin_w   = (const float*)d_in[14];
    const float* lin_b   = (const float*)d_in[15];
    const float* W1      = (const float*)d_in[16];
    const float* B1      = (const float*)d_in[17];
    const float* W2      = (const float*)d_in[18];
    const float* B2      = (const float*)d_in[19];
    const float* W3      = (const float*)d_in[20];
    const float* B3      = (const float*)d_in[21];
    float* out = (float*)d_out;

    const int smem1 = 1024*8 + (32 + 4*272 + 32 + 32) * 4;
    const int smemC = (64*76 + 64*132*2 + 64*12 + 64*20 + 64) * 4;

    cudaFuncSetAttribute(k_conv1,    cudaFuncAttributeMaxDynamicSharedMemorySize, smem1);
    cudaFuncSetAttribute(k_rbmma,    cudaFuncAttributeMaxDynamicSharedMemorySize, SM_TOTAL_M);
    cudaFuncSetAttribute(k_coupling, cudaFuncAttributeMaxDynamicSharedMemorySize, smemC);

    k_prep<<<1, 256>>>(rb_w1, rb_w2);
    k_conv1<<<BATCH, 128, smem1>>>(curve, conv1_w, conv1_b);
    k_rbmma<<<BATCH*2, 256, SM_TOTAL_M>>>(0, bn1_g, bn1_b, rb_b1);
    k_rbmma<<<BATCH*2, 256, SM_TOTAL_M>>>(1, rb_g1, rb_be1, rb_b2);
    k_pool_ctx<<<BATCH, 256>>>(bn1_g, bn1_b, rb_g2, rb_be2, lin_w, lin_b);
    k_coupling<<<BATCH/64, 256, smemC>>>(inputs, W1, B1, W2, B2, W3, B3, out);
}